// round 1
// baseline (speedup 1.0000x reference)
#include <cuda_runtime.h>
#include <math.h>

// Problem constants
#define BB 2
#define LL 2048
#define EE 2048
#define HH_ 16
#define DH 128
#define RK 512
#define RD 64
#define DTOT 192                 // DH + RD
#define QCOLS 3072               // H*(DH+RD)
#define KVCOLS 576               // RK + RD
#define UPCOLS 5120              // H*(2*DH+RD)
#define ML (BB*LL)               // 4096 rows

// -------- scratch (device globals; no runtime allocation allowed) --------
__device__ float g_qall_buf[(size_t)ML * QCOLS];          // (B,L,3072)
__device__ float g_kvlat_buf[(size_t)ML * KVCOLS];        // (B,L,576)
__device__ float g_up_buf[(size_t)ML * UPCOLS];           // (B,L,5120)
__device__ float g_q_buf[(size_t)BB * HH_ * LL * DTOT];   // (B,H,L,192)
__device__ float g_kT_buf[(size_t)BB * HH_ * DTOT * LL];  // (B,H,192,L)
__device__ float g_v_buf[(size_t)BB * HH_ * LL * DTOT];   // (B,H,L,192)
__device__ float g_scores_buf[(size_t)BB * HH_ * LL * LL];// (B,H,L,L)  ~537MB
__device__ float g_attn_buf[(size_t)ML * QCOLS];          // (B,L,H,192)

// -------- generic batched SGEMM: C = A @ B, row-major --------
// Tile: 128x64, BK=8, 256 threads, 8x4 per thread.
// Requires: M % 128 == 0, N % 64 == 0, K % 8 == 0, lda/ldb/ldc multiples of 4/2/4.
#define BM 128
#define BN 64
#define BKK 8
#define TM 8
#define TN 4

__global__ void sgemm_k(const float* __restrict__ A, const float* __restrict__ B,
                        float* __restrict__ C,
                        int M, int N, int K, int lda, int ldb, int ldc,
                        int hdiv,
                        long long sAb, long long sAh,
                        long long sBb, long long sBh,
                        long long sCb, long long sCh)
{
    int z = blockIdx.z;
    int zb = z / hdiv, zh = z % hdiv;
    A += zb * sAb + zh * sAh;
    B += zb * sBb + zh * sBh;
    C += zb * sCb + zh * sCh;

    __shared__ float As[BKK][BM];
    __shared__ float Bs[BKK][BN];

    int tid = threadIdx.x;          // 0..255
    int tx = tid & 15;              // 0..15 -> cols
    int ty = tid >> 4;              // 0..15 -> rows

    int rowBase = blockIdx.y * BM;
    int colBase = blockIdx.x * BN;

    // A loader: 4 floats per thread (float4 along K)
    int aRow = tid >> 1;            // 0..127
    int aCol = (tid & 1) * 4;       // 0 or 4
    // B loader: 2 floats per thread
    int bRow = tid >> 5;            // 0..7
    int bCol = (tid & 31) * 2;      // 0..62

    float acc[TM][TN];
#pragma unroll
    for (int i = 0; i < TM; i++)
#pragma unroll
        for (int j = 0; j < TN; j++) acc[i][j] = 0.f;

    for (int k0 = 0; k0 < K; k0 += BKK) {
        const float* Ap = A + (long long)(rowBase + aRow) * lda + (k0 + aCol);
        float4 av = *reinterpret_cast<const float4*>(Ap);
        As[aCol + 0][aRow] = av.x;
        As[aCol + 1][aRow] = av.y;
        As[aCol + 2][aRow] = av.z;
        As[aCol + 3][aRow] = av.w;

        const float* Bp = B + (long long)(k0 + bRow) * ldb + (colBase + bCol);
        float2 bv = *reinterpret_cast<const float2*>(Bp);
        Bs[bRow][bCol]     = bv.x;
        Bs[bRow][bCol + 1] = bv.y;
        __syncthreads();

#pragma unroll
        for (int k = 0; k < BKK; k++) {
            float rm[TM], rn[TN];
#pragma unroll
            for (int i = 0; i < TM; i++) rm[i] = As[k][ty * TM + i];
#pragma unroll
            for (int j = 0; j < TN; j++) rn[j] = Bs[k][tx * TN + j];
#pragma unroll
            for (int i = 0; i < TM; i++)
#pragma unroll
                for (int j = 0; j < TN; j++) acc[i][j] += rm[i] * rn[j];
        }
        __syncthreads();
    }

#pragma unroll
    for (int i = 0; i < TM; i++) {
        long long r = rowBase + ty * TM + i;
        float4 o = make_float4(acc[i][0], acc[i][1], acc[i][2], acc[i][3]);
        *reinterpret_cast<float4*>(C + r * ldc + colBase + tx * TN) = o;
    }
}

// -------- prep: RoPE(q), RoPE(k_rope), build q/(B,H,L,192), kT/(B,H,192,L), v --------
__global__ void prep_k(const float* __restrict__ qall,
                       const float* __restrict__ kvlat,
                       const float* __restrict__ up,
                       const float* __restrict__ cosT,
                       const float* __restrict__ sinT,
                       float* __restrict__ q,
                       float* __restrict__ kT,
                       float* __restrict__ v)
{
    int b = blockIdx.x / LL;
    int l = blockIdx.x % LL;
    int tid = threadIdx.x;

    __shared__ float kr[RD];

    const long long tokQ  = (long long)(b * LL + l) * QCOLS;
    const long long tokKV = (long long)(b * LL + l) * KVCOLS;
    const long long tokUP = (long long)(b * LL + l) * UPCOLS;

    if (tid < RD / 2) {
        float x1 = kvlat[tokKV + RK + 2 * tid];
        float x2 = kvlat[tokKV + RK + 2 * tid + 1];
        float c = cosT[l * (RD / 2) + tid];
        float s = sinT[l * (RD / 2) + tid];
        kr[2 * tid]     = x1 * c - x2 * s;
        kr[2 * tid + 1] = x1 * s + x2 * c;
    }
    __syncthreads();

    // q: apply rope to last 64 dims, permute to (B,H,L,192)
    for (int idx = tid; idx < HH_ * DTOT; idx += blockDim.x) {
        int h = idx / DTOT, d = idx % DTOT;
        float val;
        if (d < DH) {
            val = qall[tokQ + h * DTOT + d];
        } else {
            int i = (d - DH) >> 1;
            int odd = (d - DH) & 1;
            float x1 = qall[tokQ + h * DTOT + DH + 2 * i];
            float x2 = qall[tokQ + h * DTOT + DH + 2 * i + 1];
            float c = cosT[l * (RD / 2) + i];
            float s = sinT[l * (RD / 2) + i];
            val = odd ? (x1 * s + x2 * c) : (x1 * c - x2 * s);
        }
        q[((long long)(b * HH_ + h) * LL + l) * DTOT + d] = val;
    }

    // kT (B,H,192,L) and v (B,H,L,192)
    for (int idx = tid; idx < HH_ * DTOT; idx += blockDim.x) {
        int h = idx / DTOT, d = idx % DTOT;
        float kval = (d < DH) ? up[tokUP + h * 320 + d] : kr[d - DH];
        kT[((long long)(b * HH_ + h) * DTOT + d) * LL + l] = kval;
        float vval = (d < DH) ? up[tokUP + h * 320 + DH + d]
                              : up[tokUP + h * 320 + 2 * DH + (d - DH)];
        v[((long long)(b * HH_ + h) * LL + l) * DTOT + d] = vval;
    }
}

// -------- causal softmax over scores rows (in-place) --------
__global__ void softmax_k(float* __restrict__ scores, float scale)
{
    long long row = blockIdx.x;            // 0 .. B*H*L-1
    int l = (int)(row % LL);
    float* p = scores + row * (long long)LL;
    int valid = l + 1;
    int tid = threadIdx.x;

    __shared__ float red[256];

    float m = -1e30f;
    for (int j = tid; j < valid; j += 256) m = fmaxf(m, p[j] * scale);
    red[tid] = m; __syncthreads();
    for (int s = 128; s > 0; s >>= 1) {
        if (tid < s) red[tid] = fmaxf(red[tid], red[tid + s]);
        __syncthreads();
    }
    m = red[0]; __syncthreads();

    float sum = 0.f;
    for (int j = tid; j < valid; j += 256) {
        float e = expf(p[j] * scale - m);
        p[j] = e;
        sum += e;
    }
    red[tid] = sum; __syncthreads();
    for (int s = 128; s > 0; s >>= 1) {
        if (tid < s) red[tid] += red[tid + s];
        __syncthreads();
    }
    float inv = 1.0f / red[0];
    __syncthreads();

    for (int j = tid; j < valid; j += 256) p[j] *= inv;
    for (int j = valid + tid; j < LL; j += 256) p[j] = 0.f;
}

extern "C" void kernel_launch(void* const* d_in, const int* in_sizes, int n_in,
                              void* d_out, int out_size)
{
    const float* x     = (const float*)d_in[0];
    const float* cosT  = (const float*)d_in[1];
    const float* sinT  = (const float*)d_in[2];
    const float* wq    = (const float*)d_in[3];
    const float* wkv   = (const float*)d_in[4];
    const float* wup   = (const float*)d_in[5];
    const float* wout  = (const float*)d_in[6];
    float* out = (float*)d_out;

    static float *g_qall = nullptr, *g_kvlat, *g_up, *g_q, *g_kT, *g_v, *g_scores, *g_attn;
    if (!g_qall) {
        cudaGetSymbolAddress((void**)&g_qall,   g_qall_buf);
        cudaGetSymbolAddress((void**)&g_kvlat,  g_kvlat_buf);
        cudaGetSymbolAddress((void**)&g_up,     g_up_buf);
        cudaGetSymbolAddress((void**)&g_q,      g_q_buf);
        cudaGetSymbolAddress((void**)&g_kT,     g_kT_buf);
        cudaGetSymbolAddress((void**)&g_v,      g_v_buf);
        cudaGetSymbolAddress((void**)&g_scores, g_scores_buf);
        cudaGetSymbolAddress((void**)&g_attn,   g_attn_buf);
    }

    const long long LLL = (long long)LL;

    // 1) q_all = x @ wq         (4096 x 3072 x 2048)
    sgemm_k<<<dim3(QCOLS / BN, ML / BM, 1), 256>>>(
        x, wq, g_qall, ML, QCOLS, EE, EE, QCOLS, QCOLS,
        1, 0, 0, 0, 0, 0, 0);

    // 2) kv_lat = x @ wkv_down  (4096 x 576 x 2048)
    sgemm_k<<<dim3(KVCOLS / BN, ML / BM, 1), 256>>>(
        x, wkv, g_kvlat, ML, KVCOLS, EE, EE, KVCOLS, KVCOLS,
        1, 0, 0, 0, 0, 0, 0);

    // 3) up = c_kv @ w_up       (4096 x 5120 x 512), A row stride 576
    sgemm_k<<<dim3(UPCOLS / BN, ML / BM, 1), 256>>>(
        g_kvlat, wup, g_up, ML, UPCOLS, RK, KVCOLS, UPCOLS, UPCOLS,
        1, 0, 0, 0, 0, 0, 0);

    // 4) RoPE + layout transforms
    prep_k<<<BB * LL, 256>>>(g_qall, g_kvlat, g_up, cosT, sinT, g_q, g_kT, g_v);

    // 5) scores = q @ kT  batched over 32 (b,h): 2048 x 2048 x 192
    sgemm_k<<<dim3(LL / BN, LL / BM, BB * HH_), 256>>>(
        g_q, g_kT, g_scores, LL, LL, DTOT, DTOT, LL, LL,
        1, LLL * DTOT, 0, (long long)DTOT * LL, 0, LLL * LL, 0);

    // 6) causal softmax (scale = 1/sqrt(192))
    softmax_k<<<BB * HH_ * LL, 256>>>(g_scores, 1.0f / sqrtf((float)DTOT));

    // 7) attn_out = attn @ v  batched: 2048 x 192 x 2048, C -> (B,L,H,192)
    sgemm_k<<<dim3(DTOT / BN, LL / BM, BB * HH_), 256>>>(
        g_scores, g_v, g_attn, LL, DTOT, LL, LL, DTOT, QCOLS,
        HH_,
        (long long)HH_ * LL * LL, LLL * LL,
        (long long)HH_ * LL * DTOT, LLL * DTOT,
        LLL * QCOLS, (long long)DTOT);

    // 8) out = attn_out @ w_out (4096 x 2048 x 3072)
    sgemm_k<<<dim3(EE / BN, ML / BM, 1), 256>>>(
        g_attn, wout, out, ML, EE, QCOLS, QCOLS, EE, EE,
        1, 0, 0, 0, 0, 0, 0);
}

// round 3
// speedup vs baseline: 2.6005x; 2.6005x over previous
#include <cuda_runtime.h>
#include <cuda_bf16.h>
#include <cstdint>
#include <math.h>

typedef __nv_bfloat16 bf16;

#define BB 2
#define LL 2048
#define EE 2048
#define HH_ 16
#define DH 128
#define RK 512
#define RD 64
#define DTOT 192
#define QCOLS 3072
#define KVCOLS 576
#define UPCOLS 5120
#define ML (BB*LL)

// ===================== scratch (device globals) =====================
__device__ bf16 g_xh[(size_t)ML*EE], g_xl[(size_t)ML*EE];
__device__ bf16 g_wqTh[(size_t)QCOLS*EE], g_wqTl[(size_t)QCOLS*EE];
__device__ bf16 g_wkvTh[(size_t)KVCOLS*EE], g_wkvTl[(size_t)KVCOLS*EE];
__device__ bf16 g_wupTh[(size_t)UPCOLS*RK], g_wupTl[(size_t)UPCOLS*RK];
__device__ bf16 g_woutTh[(size_t)EE*QCOLS], g_woutTl[(size_t)EE*QCOLS];
__device__ float g_qall[(size_t)ML*QCOLS];
__device__ float g_kvlat[(size_t)ML*KVCOLS];
__device__ bf16 g_ckvh[(size_t)ML*RK], g_ckvl[(size_t)ML*RK];
__device__ float g_up[(size_t)ML*UPCOLS];
__device__ bf16 g_qhh[(size_t)BB*HH_*LL*DTOT], g_qll[(size_t)BB*HH_*LL*DTOT];
__device__ bf16 g_khh[(size_t)BB*HH_*LL*DTOT], g_kll[(size_t)BB*HH_*LL*DTOT];
__device__ bf16 g_vhh[(size_t)BB*HH_*LL*DTOT], g_vll[(size_t)BB*HH_*LL*DTOT];
__device__ bf16 g_vTh[(size_t)BB*HH_*DTOT*LL], g_vTl[(size_t)BB*HH_*DTOT*LL];
__device__ float g_scores[(size_t)BB*HH_*LL*LL];           // 537 MB
__device__ bf16 g_ath[(size_t)BB*HH_*LL*LL], g_atl[(size_t)BB*HH_*LL*LL];
__device__ bf16 g_aoh[(size_t)ML*QCOLS], g_aol[(size_t)ML*QCOLS];

// ===================== PTX helpers (baseline sm_80+ features only) =====================
__device__ __forceinline__ uint32_t smem_to_u32(const void* p) {
    uint32_t addr;
    asm("{ .reg .u64 t; cvta.to.shared.u64 t, %1; cvt.u32.u64 %0, t; }"
        : "=r"(addr) : "l"(p));
    return addr;
}
#define CP16(sdst, gsrc) \
    asm volatile("cp.async.cg.shared.global [%0], [%1], 16;" :: "r"(sdst), "l"(gsrc))
#define CP_COMMIT() asm volatile("cp.async.commit_group;" ::: "memory")
#define CP_WAIT1()  asm volatile("cp.async.wait_group 1;" ::: "memory")
#define CP_WAIT0()  asm volatile("cp.async.wait_group 0;" ::: "memory")

__device__ __forceinline__ void ldsm_x4(uint32_t* r, uint32_t a) {
    asm volatile("ldmatrix.sync.aligned.m8n8.x4.shared.b16 {%0,%1,%2,%3}, [%4];"
        : "=r"(r[0]), "=r"(r[1]), "=r"(r[2]), "=r"(r[3]) : "r"(a));
}
__device__ __forceinline__ void ldsm_x2(uint32_t* r, uint32_t a) {
    asm volatile("ldmatrix.sync.aligned.m8n8.x2.shared.b16 {%0,%1}, [%2];"
        : "=r"(r[0]), "=r"(r[1]) : "r"(a));
}
__device__ __forceinline__ void mma_bf16(float* c, const uint32_t* a, const uint32_t* b) {
    asm volatile(
        "mma.sync.aligned.m16n8k16.row.col.f32.bf16.bf16.f32 "
        "{%0,%1,%2,%3}, {%4,%5,%6,%7}, {%8,%9}, {%0,%1,%2,%3};"
        : "+f"(c[0]), "+f"(c[1]), "+f"(c[2]), "+f"(c[3])
        : "r"(a[0]), "r"(a[1]), "r"(a[2]), "r"(a[3]), "r"(b[0]), "r"(b[1]));
}
__device__ __forceinline__ void split2(float x, bf16& h, bf16& l) {
    h = __float2bfloat16(x);
    l = __float2bfloat16(x - __bfloat162float(h));
}

// ===================== warp-mma hi/lo GEMM =====================
// C[M,N] = A[M,K] @ B[N,K]^T, bf16 hi/lo inputs, fp32 accumulate.
// BM=128, BN_ in {128,64}, BK=32, 256 threads (8 warps, 2m x 4n).
// Row pad: 40 elements (80B) -> conflict-free ldmatrix.
// CAUSAL: 0 none; 1 scores (skip blocks above diagonal); 2 attn@v (K limited).
template<int BN_, int OUTMODE, int CAUSAL>
__global__ void __launch_bounds__(256)
gemm_mma(const bf16* __restrict__ Ah, const bf16* __restrict__ Al,
         const bf16* __restrict__ Bh, const bf16* __restrict__ Bl,
         float* __restrict__ C, bf16* __restrict__ Ch, bf16* __restrict__ Cl,
         int K, int lda, int ldb, int ldc, int hdiv,
         long long sAb, long long sAh2, long long sBb, long long sBh2,
         long long sCb, long long sCh2)
{
    extern __shared__ char smem[];
    const int tid = threadIdx.x;
    const int wid = tid >> 5, lane = tid & 31;

    const int z = blockIdx.z;
    const int zb = z / hdiv, zh = z % hdiv;
    {
        long long ao = (long long)zb*sAb + (long long)zh*sAh2;
        long long bo = (long long)zb*sBb + (long long)zh*sBh2;
        Ah += ao; Al += ao; Bh += bo; Bl += bo;
        long long co = (long long)zb*sCb + (long long)zh*sCh2;
        if (OUTMODE == 0) C += co; else { Ch += co; Cl += co; }
    }

    const int rowBase = blockIdx.y * 128;
    const int colBase = blockIdx.x * BN_;
    if (CAUSAL == 1 && colBase > rowBase + 127) return;

    int Keff = K;
    if (CAUSAL == 2) Keff = min(K, rowBase + 128);
    const int NC = Keff >> 5;

    constexpr int ASZ = 128 * 80;      // bytes: one A tile (128 x 32 bf16, padded)
    constexpr int BSZ = BN_ * 80;
    constexpr int STAGE = 2 * ASZ + 2 * BSZ;
    constexpr int NT = BN_ / 32;       // n-tiles of 8 per warp

    const uint32_t sbu = smem_to_u32(smem);

    const bf16* aH = Ah + (size_t)rowBase * lda;
    const bf16* aL = Al + (size_t)rowBase * lda;
    const bf16* bH = Bh + (size_t)colBase * ldb;
    const bf16* bL = Bl + (size_t)colBase * ldb;

    auto issue = [&](int c) {
        const uint32_t st = sbu + (uint32_t)(c & 1) * STAGE;
        const int k0 = c << 5;
#pragma unroll
        for (int it = 0; it < 2; it++) {           // A tiles: 512 16B-chunks each
            int idx = tid + it * 256;
            int row = idx >> 2, seg = (idx & 3) << 3;   // seg in elements
            size_t go = (size_t)row * lda + k0 + seg;
            uint32_t so = st + row * 80 + (seg << 1);
            CP16(so, aH + go);
            CP16(so + ASZ, aL + go);
        }
#pragma unroll
        for (int it = 0; it < BN_ / 64; it++) {    // B tiles: BN_*4 chunks each
            int idx = tid + it * 256;
            int row = idx >> 2, seg = (idx & 3) << 3;
            size_t go = (size_t)row * ldb + k0 + seg;
            uint32_t so = st + 2 * ASZ + row * 80 + (seg << 1);
            CP16(so, bH + go);
            CP16(so + BSZ, bL + go);
        }
        CP_COMMIT();
    };

    float acc[4][NT][4];
#pragma unroll
    for (int mt = 0; mt < 4; mt++)
#pragma unroll
        for (int nt = 0; nt < NT; nt++)
#pragma unroll
            for (int j = 0; j < 4; j++) acc[mt][nt][j] = 0.f;

    const int wm = wid & 1, wn = wid >> 1;

    issue(0);
    for (int c = 0; c < NC; c++) {
        if (c + 1 < NC) { issue(c + 1); CP_WAIT1(); } else { CP_WAIT0(); }
        __syncthreads();

        const uint32_t st = sbu + (uint32_t)(c & 1) * STAGE;
        const uint32_t sA = st, sB = st + 2 * ASZ;

#pragma unroll
        for (int ks = 0; ks < 2; ks++) {
            uint32_t bh_[NT][2], bl_[NT][2];
#pragma unroll
            for (int nt = 0; nt < NT; nt++) {
                int rrow = wn * (BN_ / 4) + nt * 8 + (lane & 7);
                int ccol = ks * 16 + ((lane >> 3) & 1) * 8;
                uint32_t addr = sB + rrow * 80 + ccol * 2;
                ldsm_x2(bh_[nt], addr);
                ldsm_x2(bl_[nt], addr + BSZ);
            }
#pragma unroll
            for (int mt = 0; mt < 4; mt++) {
                int arow = wm * 64 + mt * 16 + (lane & 15);
                int acol = ks * 16 + (lane >> 4) * 8;
                uint32_t aaddr = sA + arow * 80 + acol * 2;
                uint32_t ah_[4], al_[4];
                ldsm_x4(ah_, aaddr);
                ldsm_x4(al_, aaddr + ASZ);
#pragma unroll
                for (int nt = 0; nt < NT; nt++) {
                    mma_bf16(acc[mt][nt], ah_, bh_[nt]);
                    mma_bf16(acc[mt][nt], ah_, bl_[nt]);
                    mma_bf16(acc[mt][nt], al_, bh_[nt]);
                }
            }
        }
        __syncthreads();
    }

    // epilogue
#pragma unroll
    for (int mt = 0; mt < 4; mt++) {
        size_t r0 = (size_t)rowBase + wm * 64 + mt * 16 + (lane >> 2);
#pragma unroll
        for (int nt = 0; nt < NT; nt++) {
            int c0 = colBase + wn * (BN_ / 4) + nt * 8 + 2 * (lane & 3);
            if (OUTMODE == 0) {
                *(float2*)(C + r0 * ldc + c0) =
                    make_float2(acc[mt][nt][0], acc[mt][nt][1]);
                *(float2*)(C + (r0 + 8) * ldc + c0) =
                    make_float2(acc[mt][nt][2], acc[mt][nt][3]);
            } else {
                bf16 h0, l0, h1, l1;
                split2(acc[mt][nt][0], h0, l0); split2(acc[mt][nt][1], h1, l1);
                *(__nv_bfloat162*)(Ch + r0 * ldc + c0) = __halves2bfloat162(h0, h1);
                *(__nv_bfloat162*)(Cl + r0 * ldc + c0) = __halves2bfloat162(l0, l1);
                split2(acc[mt][nt][2], h0, l0); split2(acc[mt][nt][3], h1, l1);
                *(__nv_bfloat162*)(Ch + (r0 + 8) * ldc + c0) = __halves2bfloat162(h0, h1);
                *(__nv_bfloat162*)(Cl + (r0 + 8) * ldc + c0) = __halves2bfloat162(l0, l1);
            }
        }
    }
}

// ===================== small kernels =====================
__global__ void split_k(const float* __restrict__ in, bf16* __restrict__ oh,
                        bf16* __restrict__ ol, int cols, int ldin)
{
    size_t idx = (size_t)blockIdx.x*256 + threadIdx.x;
    size_t row = idx / cols, col = idx % cols;
    float v = in[row*(size_t)ldin + col];
    bf16 h, l; split2(v, h, l);
    oh[idx] = h; ol[idx] = l;
}

__global__ void wtrans_k(const float* __restrict__ W, bf16* __restrict__ oh,
                         bf16* __restrict__ ol, int Kd, int Nd)
{
    __shared__ float t[32][33];
    int k0 = blockIdx.y*32, n0 = blockIdx.x*32;
    int tx = threadIdx.x, ty = threadIdx.y;
    for (int r = ty; r < 32; r += 8)
        t[r][tx] = W[(size_t)(k0+r)*Nd + n0 + tx];
    __syncthreads();
    for (int r = ty; r < 32; r += 8) {
        float v = t[tx][r];
        bf16 h, l; split2(v, h, l);
        size_t o = (size_t)(n0+r)*Kd + k0 + tx;
        oh[o] = h; ol[o] = l;
    }
}

__global__ void prep_k(const float* __restrict__ qall, const float* __restrict__ kvlat,
                       const float* __restrict__ up, const float* __restrict__ cosT,
                       const float* __restrict__ sinT,
                       bf16* __restrict__ qh, bf16* __restrict__ ql,
                       bf16* __restrict__ kh, bf16* __restrict__ kl,
                       bf16* __restrict__ vh, bf16* __restrict__ vl)
{
    int b = blockIdx.x / LL;
    int l = blockIdx.x % LL;
    int tid = threadIdx.x;
    __shared__ float kr[RD];

    const size_t tokQ  = (size_t)(b*LL + l) * QCOLS;
    const size_t tokKV = (size_t)(b*LL + l) * KVCOLS;
    const size_t tokUP = (size_t)(b*LL + l) * UPCOLS;

    if (tid < RD/2) {
        float x1 = kvlat[tokKV + RK + 2*tid];
        float x2 = kvlat[tokKV + RK + 2*tid + 1];
        float c = cosT[l*(RD/2) + tid];
        float s = sinT[l*(RD/2) + tid];
        kr[2*tid]   = x1*c - x2*s;
        kr[2*tid+1] = x1*s + x2*c;
    }
    __syncthreads();

    for (int idx = tid; idx < HH_*DTOT; idx += blockDim.x) {
        int h = idx / DTOT, d = idx % DTOT;
        size_t o = ((size_t)(b*HH_ + h)*LL + l)*DTOT + d;
        float qv;
        if (d < DH) qv = qall[tokQ + h*DTOT + d];
        else {
            int i = (d - DH) >> 1, odd = (d - DH) & 1;
            float x1 = qall[tokQ + h*DTOT + DH + 2*i];
            float x2 = qall[tokQ + h*DTOT + DH + 2*i + 1];
            float c = cosT[l*(RD/2) + i], s = sinT[l*(RD/2) + i];
            qv = odd ? (x1*s + x2*c) : (x1*c - x2*s);
        }
        bf16 hh, lo; split2(qv, hh, lo); qh[o] = hh; ql[o] = lo;
        float kv = (d < DH) ? up[tokUP + h*320 + d] : kr[d - DH];
        split2(kv, hh, lo); kh[o] = hh; kl[o] = lo;
        float vv = (d < DH) ? up[tokUP + h*320 + DH + d]
                            : up[tokUP + h*320 + 2*DH + (d - DH)];
        split2(vv, hh, lo); vh[o] = hh; vl[o] = lo;
    }
}

__global__ void vtrans_k(const bf16* __restrict__ inh, const bf16* __restrict__ inl,
                         bf16* __restrict__ outh, bf16* __restrict__ outl)
{
    __shared__ bf16 t[32][33];
    int z = blockIdx.z;
    int l0 = blockIdx.x*32, d0 = blockIdx.y*32;
    int tx = threadIdx.x, ty = threadIdx.y;
    const size_t ibase = (size_t)z*LL*DTOT;
    const size_t obase = (size_t)z*DTOT*LL;
#pragma unroll
    for (int a = 0; a < 2; a++) {
        const bf16* in = a ? inl : inh;
        bf16* out = a ? outl : outh;
        for (int r = ty; r < 32; r += 8)
            t[r][tx] = in[ibase + (size_t)(l0+r)*DTOT + d0 + tx];
        __syncthreads();
        for (int r = ty; r < 32; r += 8)
            out[obase + (size_t)(d0+r)*LL + l0 + tx] = t[tx][r];
        __syncthreads();
    }
}

// causal softmax; zero-fill only up to the 128-block boundary (attn@v K-limit)
__global__ void softmax_k(const float* __restrict__ scores, bf16* __restrict__ ah,
                          bf16* __restrict__ al, float scale)
{
    size_t row = blockIdx.x;
    int l = (int)(row % LL);
    const float* p = scores + row*(size_t)LL;
    bf16* oh = ah + row*(size_t)LL;
    bf16* ol = al + row*(size_t)LL;
    int valid = l + 1;
    int zlim = ((l >> 7) + 1) << 7;
    int tid = threadIdx.x;
    __shared__ float red[256];

    float m = -1e30f;
    for (int j = tid; j < valid; j += 256) m = fmaxf(m, p[j]*scale);
    red[tid] = m; __syncthreads();
    for (int s = 128; s > 0; s >>= 1) {
        if (tid < s) red[tid] = fmaxf(red[tid], red[tid+s]);
        __syncthreads();
    }
    m = red[0]; __syncthreads();

    float sum = 0.f;
    for (int j = tid; j < valid; j += 256) sum += __expf(p[j]*scale - m);
    red[tid] = sum; __syncthreads();
    for (int s = 128; s > 0; s >>= 1) {
        if (tid < s) red[tid] += red[tid+s];
        __syncthreads();
    }
    float inv = 1.0f / red[0];
    __syncthreads();

    for (int j = tid; j < valid; j += 256) {
        float e = __expf(p[j]*scale - m) * inv;
        bf16 h, lo; split2(e, h, lo);
        oh[j] = h; ol[j] = lo;
    }
    bf16 z0 = __float2bfloat16(0.f);
    for (int j = valid + tid; j < zlim; j += 256) { oh[j] = z0; ol[j] = z0; }
}

// ===================== launch =====================
extern "C" void kernel_launch(void* const* d_in, const int* in_sizes, int n_in,
                              void* d_out, int out_size)
{
    const float* x    = (const float*)d_in[0];
    const float* cosT = (const float*)d_in[1];
    const float* sinT = (const float*)d_in[2];
    const float* wq   = (const float*)d_in[3];
    const float* wkv  = (const float*)d_in[4];
    const float* wup  = (const float*)d_in[5];
    const float* wout = (const float*)d_in[6];
    float* out = (float*)d_out;

    static bool init = false;
    static bf16 *xh,*xl,*wqTh,*wqTl,*wkvTh,*wkvTl,*wupTh,*wupTl,*woutTh,*woutTl;
    static float *qall,*kvlat,*up,*scores;
    static bf16 *ckvh,*ckvl,*qhh,*qll,*khh,*kll,*vhh,*vll,*vTh,*vTl,*ath,*atl,*aoh,*aol;
    if (!init) {
        cudaGetSymbolAddress((void**)&xh, g_xh);     cudaGetSymbolAddress((void**)&xl, g_xl);
        cudaGetSymbolAddress((void**)&wqTh, g_wqTh); cudaGetSymbolAddress((void**)&wqTl, g_wqTl);
        cudaGetSymbolAddress((void**)&wkvTh, g_wkvTh); cudaGetSymbolAddress((void**)&wkvTl, g_wkvTl);
        cudaGetSymbolAddress((void**)&wupTh, g_wupTh); cudaGetSymbolAddress((void**)&wupTl, g_wupTl);
        cudaGetSymbolAddress((void**)&woutTh, g_woutTh); cudaGetSymbolAddress((void**)&woutTl, g_woutTl);
        cudaGetSymbolAddress((void**)&qall, g_qall); cudaGetSymbolAddress((void**)&kvlat, g_kvlat);
        cudaGetSymbolAddress((void**)&up, g_up);     cudaGetSymbolAddress((void**)&scores, g_scores);
        cudaGetSymbolAddress((void**)&ckvh, g_ckvh); cudaGetSymbolAddress((void**)&ckvl, g_ckvl);
        cudaGetSymbolAddress((void**)&qhh, g_qhh);   cudaGetSymbolAddress((void**)&qll, g_qll);
        cudaGetSymbolAddress((void**)&khh, g_khh);   cudaGetSymbolAddress((void**)&kll, g_kll);
        cudaGetSymbolAddress((void**)&vhh, g_vhh);   cudaGetSymbolAddress((void**)&vll, g_vll);
        cudaGetSymbolAddress((void**)&vTh, g_vTh);   cudaGetSymbolAddress((void**)&vTl, g_vTl);
        cudaGetSymbolAddress((void**)&ath, g_ath);   cudaGetSymbolAddress((void**)&atl, g_atl);
        cudaGetSymbolAddress((void**)&aoh, g_aoh);   cudaGetSymbolAddress((void**)&aol, g_aol);
        cudaFuncSetAttribute((const void*)gemm_mma<128,0,0>,
                             cudaFuncAttributeMaxDynamicSharedMemorySize, 2*(2*128*80 + 2*128*80));
        cudaFuncSetAttribute((const void*)gemm_mma<128,0,1>,
                             cudaFuncAttributeMaxDynamicSharedMemorySize, 2*(2*128*80 + 2*128*80));
        cudaFuncSetAttribute((const void*)gemm_mma<64,0,0>,
                             cudaFuncAttributeMaxDynamicSharedMemorySize, 2*(2*128*80 + 2*64*80));
        cudaFuncSetAttribute((const void*)gemm_mma<64,1,2>,
                             cudaFuncAttributeMaxDynamicSharedMemorySize, 2*(2*128*80 + 2*64*80));
        init = true;
    }
    const int SM128 = 2*(2*128*80 + 2*128*80);   // 81920
    const int SM64  = 2*(2*128*80 + 2*64*80);    // 61440
    const long long LLL = (long long)LL;

    // convert inputs to bf16 hi/lo (weights transposed to [N][K])
    split_k<<<(ML*EE)/256, 256>>>(x, xh, xl, EE, EE);
    wtrans_k<<<dim3(QCOLS/32, EE/32), dim3(32,8)>>>(wq, wqTh, wqTl, EE, QCOLS);
    wtrans_k<<<dim3(KVCOLS/32, EE/32), dim3(32,8)>>>(wkv, wkvTh, wkvTl, EE, KVCOLS);
    wtrans_k<<<dim3(UPCOLS/32, RK/32), dim3(32,8)>>>(wup, wupTh, wupTl, RK, UPCOLS);
    wtrans_k<<<dim3(EE/32, QCOLS/32), dim3(32,8)>>>(wout, woutTh, woutTl, QCOLS, EE);

    // 1) qall = x @ wq (4096x3072x2048)
    gemm_mma<128,0,0><<<dim3(QCOLS/128, ML/128, 1), 256, SM128>>>(
        xh, xl, wqTh, wqTl, qall, nullptr, nullptr,
        EE, EE, EE, QCOLS, 1, 0,0,0,0,0,0);

    // 2) kvlat = x @ wkv (4096x576x2048)
    gemm_mma<64,0,0><<<dim3(KVCOLS/64, ML/128, 1), 256, SM64>>>(
        xh, xl, wkvTh, wkvTl, kvlat, nullptr, nullptr,
        EE, EE, EE, KVCOLS, 1, 0,0,0,0,0,0);

    // split c_kv
    split_k<<<(ML*RK)/256, 256>>>(kvlat, ckvh, ckvl, RK, KVCOLS);

    // 3) up = ckv @ wup (4096x5120x512)
    gemm_mma<128,0,0><<<dim3(UPCOLS/128, ML/128, 1), 256, SM128>>>(
        ckvh, ckvl, wupTh, wupTl, up, nullptr, nullptr,
        RK, RK, RK, UPCOLS, 1, 0,0,0,0,0,0);

    // 4) rope + build q,k,v
    prep_k<<<BB*LL, 256>>>(qall, kvlat, up, cosT, sinT, qhh, qll, khh, kll, vhh, vll);

    // 5) v -> vT
    vtrans_k<<<dim3(LL/32, DTOT/32, BB*HH_), dim3(32,8)>>>(vhh, vll, vTh, vTl);

    // 6) scores = q @ k^T (batched 32, causal block skip)
    gemm_mma<128,0,1><<<dim3(LL/128, LL/128, BB*HH_), 256, SM128>>>(
        qhh, qll, khh, kll, scores, nullptr, nullptr,
        DTOT, DTOT, DTOT, LL, BB*HH_,
        0, LLL*DTOT, 0, LLL*DTOT, 0, LLL*LL);

    // 7) softmax -> attn hi/lo
    softmax_k<<<BB*HH_*LL, 256>>>(scores, ath, atl, 1.0f/sqrtf((float)DTOT));

    // 8) attnout = attn @ vT (batched, K limited by causality), bf16 hi/lo out
    gemm_mma<64,1,2><<<dim3(DTOT/64, LL/128, BB*HH_), 256, SM64>>>(
        ath, atl, vTh, vTl, nullptr, aoh, aol,
        LL, LL, LL, QCOLS, HH_,
        (long long)HH_*LL*LL, LLL*LL,
        (long long)HH_*DTOT*LL, (long long)DTOT*LL,
        LLL*QCOLS, (long long)DTOT);

    // 9) out = attnout @ wout (4096x2048x3072)
    gemm_mma<128,0,0><<<dim3(EE/128, ML/128, 1), 256, SM128>>>(
        aoh, aol, woutTh, woutTl, out, nullptr, nullptr,
        QCOLS, QCOLS, QCOLS, EE, 1, 0,0,0,0,0,0);
}

// round 4
// speedup vs baseline: 2.7042x; 1.0399x over previous
#include <cuda_runtime.h>
#include <cuda_bf16.h>
#include <cstdint>
#include <math.h>

typedef __nv_bfloat16 bf16;

#define BB 2
#define LL 2048
#define EE 2048
#define HH_ 16
#define DH 128
#define RK 512
#define RD 64
#define DTOT 192
#define QCOLS 3072
#define KVCOLS 576
#define UPCOLS 5120
#define ML (BB*LL)

// ===================== scratch (device globals) =====================
__device__ bf16 g_xh[(size_t)ML*EE], g_xl[(size_t)ML*EE];
__device__ bf16 g_wqTh[(size_t)QCOLS*EE], g_wqTl[(size_t)QCOLS*EE];
__device__ bf16 g_wkvTh[(size_t)KVCOLS*EE], g_wkvTl[(size_t)KVCOLS*EE];
__device__ bf16 g_wupTh[(size_t)UPCOLS*RK], g_wupTl[(size_t)UPCOLS*RK];
__device__ bf16 g_woutTh[(size_t)EE*QCOLS], g_woutTl[(size_t)EE*QCOLS];
__device__ float g_qall[(size_t)ML*QCOLS];
__device__ float g_kvlat[(size_t)ML*KVCOLS];
__device__ bf16 g_ckvh[(size_t)ML*RK], g_ckvl[(size_t)ML*RK];
__device__ float g_up[(size_t)ML*UPCOLS];
__device__ bf16 g_qhh[(size_t)BB*HH_*LL*DTOT], g_qll[(size_t)BB*HH_*LL*DTOT];
__device__ bf16 g_khh[(size_t)BB*HH_*LL*DTOT], g_kll[(size_t)BB*HH_*LL*DTOT];
__device__ bf16 g_vhh[(size_t)BB*HH_*LL*DTOT], g_vll[(size_t)BB*HH_*LL*DTOT];
__device__ bf16 g_vTh[(size_t)BB*HH_*DTOT*LL], g_vTl[(size_t)BB*HH_*DTOT*LL];
__device__ float g_scores[(size_t)BB*HH_*LL*LL];           // 537 MB
__device__ bf16 g_ath[(size_t)BB*HH_*LL*LL], g_atl[(size_t)BB*HH_*LL*LL];
__device__ bf16 g_aoh[(size_t)ML*QCOLS], g_aol[(size_t)ML*QCOLS];

// ===================== PTX helpers (baseline sm_80+ features only) =====================
__device__ __forceinline__ uint32_t smem_to_u32(const void* p) {
    uint32_t addr;
    asm("{ .reg .u64 t; cvta.to.shared.u64 t, %1; cvt.u32.u64 %0, t; }"
        : "=r"(addr) : "l"(p));
    return addr;
}
#define CP16(sdst, gsrc) \
    asm volatile("cp.async.cg.shared.global [%0], [%1], 16;" :: "r"(sdst), "l"(gsrc))
#define CP_COMMIT() asm volatile("cp.async.commit_group;" ::: "memory")
#define CP_WAIT1()  asm volatile("cp.async.wait_group 1;" ::: "memory")

__device__ __forceinline__ void ldsm_x4(uint32_t* r, uint32_t a) {
    asm volatile("ldmatrix.sync.aligned.m8n8.x4.shared.b16 {%0,%1,%2,%3}, [%4];"
        : "=r"(r[0]), "=r"(r[1]), "=r"(r[2]), "=r"(r[3]) : "r"(a));
}
__device__ __forceinline__ void mma_bf16(float* c, const uint32_t* a, const uint32_t* b) {
    asm volatile(
        "mma.sync.aligned.m16n8k16.row.col.f32.bf16.bf16.f32 "
        "{%0,%1,%2,%3}, {%4,%5,%6,%7}, {%8,%9}, {%0,%1,%2,%3};"
        : "+f"(c[0]), "+f"(c[1]), "+f"(c[2]), "+f"(c[3])
        : "r"(a[0]), "r"(a[1]), "r"(a[2]), "r"(a[3]), "r"(b[0]), "r"(b[1]));
}
__device__ __forceinline__ void split2(float x, bf16& h, bf16& l) {
    h = __float2bfloat16(x);
    l = __float2bfloat16(x - __bfloat162float(h));
}

// ===================== warp-mma hi/lo GEMM (3-stage pipeline) =====================
// C[M,N] = A[M,K] @ B[N,K]^T, bf16 hi/lo inputs, fp32 accumulate.
// BM=128, BN_ in {128,64}, BK=32, 256 threads (8 warps, 2m x 4n).
// Row pad 80B -> conflict-free ldmatrix. 3 SMEM stages, one barrier/chunk,
// empty-commit-group trick keeps wait_group(1) valid at the tail.
// CAUSAL: 0 none; 1 scores (skip blocks above diagonal); 2 attn@v (K limited).
template<int BN_, int OUTMODE, int CAUSAL>
__global__ void __launch_bounds__(256)
gemm_mma(const bf16* __restrict__ Ah, const bf16* __restrict__ Al,
         const bf16* __restrict__ Bh, const bf16* __restrict__ Bl,
         float* __restrict__ C, bf16* __restrict__ Ch, bf16* __restrict__ Cl,
         int K, int lda, int ldb, int ldc, int hdiv,
         long long sAb, long long sAh2, long long sBb, long long sBh2,
         long long sCb, long long sCh2)
{
    extern __shared__ char smem[];
    const int tid = threadIdx.x;
    const int wid = tid >> 5, lane = tid & 31;

    const int z = blockIdx.z;
    const int zb = z / hdiv, zh = z % hdiv;
    {
        long long ao = (long long)zb*sAb + (long long)zh*sAh2;
        long long bo = (long long)zb*sBb + (long long)zh*sBh2;
        Ah += ao; Al += ao; Bh += bo; Bl += bo;
        long long co = (long long)zb*sCb + (long long)zh*sCh2;
        if (OUTMODE == 0) C += co; else { Ch += co; Cl += co; }
    }

    const int rowBase = blockIdx.y * 128;
    const int colBase = blockIdx.x * BN_;
    if (CAUSAL == 1 && colBase > rowBase + 127) return;

    int Keff = K;
    if (CAUSAL == 2) Keff = min(K, rowBase + 128);
    const int NC = Keff >> 5;

    constexpr int ASZ = 128 * 80;      // one A component tile (128 x 32 bf16, 80B rows)
    constexpr int BSZ = BN_ * 80;
    constexpr int STAGE = 2 * ASZ + 2 * BSZ;
    constexpr int NT = BN_ / 32;       // n-tiles of 8 per warp

    const uint32_t sbu = smem_to_u32(smem);

    const bf16* aH = Ah + (size_t)rowBase * lda;
    const bf16* aL = Al + (size_t)rowBase * lda;
    const bf16* bH = Bh + (size_t)colBase * ldb;
    const bf16* bL = Bl + (size_t)colBase * ldb;

    auto issue = [&](int c) {
        const uint32_t st = sbu + (uint32_t)(c % 3) * STAGE;
        const int k0 = c << 5;
#pragma unroll
        for (int it = 0; it < 2; it++) {           // A: 128 rows x 2 comps
            int idx = tid + it * 256;
            int row = idx >> 2, seg = (idx & 3) << 3;
            size_t go = (size_t)row * lda + k0 + seg;
            uint32_t so = st + row * 80 + (seg << 1);
            CP16(so, aH + go);
            CP16(so + ASZ, aL + go);
        }
#pragma unroll
        for (int it = 0; it < BN_ / 64; it++) {    // B: BN_ rows x 2 comps
            int idx = tid + it * 256;
            int row = idx >> 2, seg = (idx & 3) << 3;
            size_t go = (size_t)row * ldb + k0 + seg;
            uint32_t so = st + 2 * ASZ + row * 80 + (seg << 1);
            CP16(so, bH + go);
            CP16(so + BSZ, bL + go);
        }
        CP_COMMIT();
    };

    float acc[4][NT][4];
#pragma unroll
    for (int mt = 0; mt < 4; mt++)
#pragma unroll
        for (int nt = 0; nt < NT; nt++)
#pragma unroll
            for (int j = 0; j < 4; j++) acc[mt][nt][j] = 0.f;

    const int wm = wid & 1, wn = wid >> 1;

    // prologue: exactly 2 groups committed (real or empty)
    if (0 < NC) issue(0); else CP_COMMIT();
    if (1 < NC) issue(1); else CP_COMMIT();

    for (int c = 0; c < NC; c++) {
        CP_WAIT1();
        __syncthreads();
        if (c + 2 < NC) issue(c + 2); else CP_COMMIT();

        const uint32_t st = sbu + (uint32_t)(c % 3) * STAGE;
        const uint32_t sA = st, sB = st + 2 * ASZ;

        // hoist all B fragments for this chunk (x4 = two n-tiles per ldsm)
        uint32_t bh_[2][NT][2], bl_[2][NT][2];
#pragma unroll
        for (int ks = 0; ks < 2; ks++)
#pragma unroll
            for (int p = 0; p < NT / 2; p++) {
                int rrow = wn * (BN_ / 4) + p * 16 + ((lane >> 4) & 1) * 8 + (lane & 7);
                int ccol = ks * 16 + ((lane >> 3) & 1) * 8;
                uint32_t addr = sB + rrow * 80 + ccol * 2;
                uint32_t t4[4];
                ldsm_x4(t4, addr);
                bh_[ks][2*p][0] = t4[0]; bh_[ks][2*p][1] = t4[1];
                bh_[ks][2*p+1][0] = t4[2]; bh_[ks][2*p+1][1] = t4[3];
                ldsm_x4(t4, addr + BSZ);
                bl_[ks][2*p][0] = t4[0]; bl_[ks][2*p][1] = t4[1];
                bl_[ks][2*p+1][0] = t4[2]; bl_[ks][2*p+1][1] = t4[3];
            }

        // A fragments double-buffered over t = mt*2 + ks
        uint32_t ah2[2][4], al2[2][4];
        {
            int arow = wm * 64 + (lane & 15);
            int acol = (lane >> 4) * 8;
            uint32_t a = sA + arow * 80 + acol * 2;
            ldsm_x4(ah2[0], a); ldsm_x4(al2[0], a + ASZ);
        }
#pragma unroll
        for (int t = 0; t < 8; t++) {
            const int cur = t & 1;
            if (t < 7) {
                int t1 = t + 1, mt1 = t1 >> 1, ks1 = t1 & 1;
                int arow = wm * 64 + mt1 * 16 + (lane & 15);
                int acol = ks1 * 16 + (lane >> 4) * 8;
                uint32_t a = sA + arow * 80 + acol * 2;
                ldsm_x4(ah2[cur ^ 1], a); ldsm_x4(al2[cur ^ 1], a + ASZ);
            }
            const int mt = t >> 1, ks = t & 1;
#pragma unroll
            for (int nt = 0; nt < NT; nt++) {
                mma_bf16(acc[mt][nt], ah2[cur], bh_[ks][nt]);
                mma_bf16(acc[mt][nt], ah2[cur], bl_[ks][nt]);
                mma_bf16(acc[mt][nt], al2[cur], bh_[ks][nt]);
            }
        }
    }

    // epilogue
#pragma unroll
    for (int mt = 0; mt < 4; mt++) {
        size_t r0 = (size_t)rowBase + wm * 64 + mt * 16 + (lane >> 2);
#pragma unroll
        for (int nt = 0; nt < NT; nt++) {
            int c0 = colBase + wn * (BN_ / 4) + nt * 8 + 2 * (lane & 3);
            if (OUTMODE == 0) {
                *(float2*)(C + r0 * ldc + c0) =
                    make_float2(acc[mt][nt][0], acc[mt][nt][1]);
                *(float2*)(C + (r0 + 8) * ldc + c0) =
                    make_float2(acc[mt][nt][2], acc[mt][nt][3]);
            } else {
                bf16 h0, l0, h1, l1;
                split2(acc[mt][nt][0], h0, l0); split2(acc[mt][nt][1], h1, l1);
                *(__nv_bfloat162*)(Ch + r0 * ldc + c0) = __halves2bfloat162(h0, h1);
                *(__nv_bfloat162*)(Cl + r0 * ldc + c0) = __halves2bfloat162(l0, l1);
                split2(acc[mt][nt][2], h0, l0); split2(acc[mt][nt][3], h1, l1);
                *(__nv_bfloat162*)(Ch + (r0 + 8) * ldc + c0) = __halves2bfloat162(h0, h1);
                *(__nv_bfloat162*)(Cl + (r0 + 8) * ldc + c0) = __halves2bfloat162(l0, l1);
            }
        }
    }
}

// ===================== small kernels =====================
__global__ void split_k(const float* __restrict__ in, bf16* __restrict__ oh,
                        bf16* __restrict__ ol, int cols, int ldin)
{
    size_t idx = (size_t)blockIdx.x*256 + threadIdx.x;
    size_t row = idx / cols, col = idx % cols;
    float v = in[row*(size_t)ldin + col];
    bf16 h, l; split2(v, h, l);
    oh[idx] = h; ol[idx] = l;
}

__global__ void wtrans_k(const float* __restrict__ W, bf16* __restrict__ oh,
                         bf16* __restrict__ ol, int Kd, int Nd)
{
    __shared__ float t[32][33];
    int k0 = blockIdx.y*32, n0 = blockIdx.x*32;
    int tx = threadIdx.x, ty = threadIdx.y;
    for (int r = ty; r < 32; r += 8)
        t[r][tx] = W[(size_t)(k0+r)*Nd + n0 + tx];
    __syncthreads();
    for (int r = ty; r < 32; r += 8) {
        float v = t[tx][r];
        bf16 h, l; split2(v, h, l);
        size_t o = (size_t)(n0+r)*Kd + k0 + tx;
        oh[o] = h; ol[o] = l;
    }
}

__global__ void prep_k(const float* __restrict__ qall, const float* __restrict__ kvlat,
                       const float* __restrict__ up, const float* __restrict__ cosT,
                       const float* __restrict__ sinT,
                       bf16* __restrict__ qh, bf16* __restrict__ ql,
                       bf16* __restrict__ kh, bf16* __restrict__ kl,
                       bf16* __restrict__ vh, bf16* __restrict__ vl)
{
    int b = blockIdx.x / LL;
    int l = blockIdx.x % LL;
    int tid = threadIdx.x;
    __shared__ float kr[RD];

    const size_t tokQ  = (size_t)(b*LL + l) * QCOLS;
    const size_t tokKV = (size_t)(b*LL + l) * KVCOLS;
    const size_t tokUP = (size_t)(b*LL + l) * UPCOLS;

    if (tid < RD/2) {
        float x1 = kvlat[tokKV + RK + 2*tid];
        float x2 = kvlat[tokKV + RK + 2*tid + 1];
        float c = cosT[l*(RD/2) + tid];
        float s = sinT[l*(RD/2) + tid];
        kr[2*tid]   = x1*c - x2*s;
        kr[2*tid+1] = x1*s + x2*c;
    }
    __syncthreads();

    for (int idx = tid; idx < HH_*DTOT; idx += blockDim.x) {
        int h = idx / DTOT, d = idx % DTOT;
        size_t o = ((size_t)(b*HH_ + h)*LL + l)*DTOT + d;
        float qv;
        if (d < DH) qv = qall[tokQ + h*DTOT + d];
        else {
            int i = (d - DH) >> 1, odd = (d - DH) & 1;
            float x1 = qall[tokQ + h*DTOT + DH + 2*i];
            float x2 = qall[tokQ + h*DTOT + DH + 2*i + 1];
            float c = cosT[l*(RD/2) + i], s = sinT[l*(RD/2) + i];
            qv = odd ? (x1*s + x2*c) : (x1*c - x2*s);
        }
        bf16 hh, lo; split2(qv, hh, lo); qh[o] = hh; ql[o] = lo;
        float kv = (d < DH) ? up[tokUP + h*320 + d] : kr[d - DH];
        split2(kv, hh, lo); kh[o] = hh; kl[o] = lo;
        float vv = (d < DH) ? up[tokUP + h*320 + DH + d]
                            : up[tokUP + h*320 + 2*DH + (d - DH)];
        split2(vv, hh, lo); vh[o] = hh; vl[o] = lo;
    }
}

__global__ void vtrans_k(const bf16* __restrict__ inh, const bf16* __restrict__ inl,
                         bf16* __restrict__ outh, bf16* __restrict__ outl)
{
    __shared__ bf16 t[32][33];
    int z = blockIdx.z;
    int l0 = blockIdx.x*32, d0 = blockIdx.y*32;
    int tx = threadIdx.x, ty = threadIdx.y;
    const size_t ibase = (size_t)z*LL*DTOT;
    const size_t obase = (size_t)z*DTOT*LL;
#pragma unroll
    for (int a = 0; a < 2; a++) {
        const bf16* in = a ? inl : inh;
        bf16* out = a ? outl : outh;
        for (int r = ty; r < 32; r += 8)
            t[r][tx] = in[ibase + (size_t)(l0+r)*DTOT + d0 + tx];
        __syncthreads();
        for (int r = ty; r < 32; r += 8)
            out[obase + (size_t)(d0+r)*LL + l0 + tx] = t[tx][r];
        __syncthreads();
    }
}

// causal softmax; zero-fill only up to the 128-block boundary (attn@v K-limit)
__global__ void softmax_k(const float* __restrict__ scores, bf16* __restrict__ ah,
                          bf16* __restrict__ al, float scale)
{
    size_t row = blockIdx.x;
    int l = (int)(row % LL);
    const float* p = scores + row*(size_t)LL;
    bf16* oh = ah + row*(size_t)LL;
    bf16* ol = al + row*(size_t)LL;
    int valid = l + 1;
    int zlim = ((l >> 7) + 1) << 7;
    int tid = threadIdx.x;
    __shared__ float red[256];

    float m = -1e30f;
    for (int j = tid; j < valid; j += 256) m = fmaxf(m, p[j]*scale);
    red[tid] = m; __syncthreads();
    for (int s = 128; s > 0; s >>= 1) {
        if (tid < s) red[tid] = fmaxf(red[tid], red[tid+s]);
        __syncthreads();
    }
    m = red[0]; __syncthreads();

    float sum = 0.f;
    for (int j = tid; j < valid; j += 256) sum += __expf(p[j]*scale - m);
    red[tid] = sum; __syncthreads();
    for (int s = 128; s > 0; s >>= 1) {
        if (tid < s) red[tid] += red[tid+s];
        __syncthreads();
    }
    float inv = 1.0f / red[0];
    __syncthreads();

    for (int j = tid; j < valid; j += 256) {
        float e = __expf(p[j]*scale - m) * inv;
        bf16 h, lo; split2(e, h, lo);
        oh[j] = h; ol[j] = lo;
    }
    bf16 z0 = __float2bfloat16(0.f);
    for (int j = valid + tid; j < zlim; j += 256) { oh[j] = z0; ol[j] = z0; }
}

// ===================== launch =====================
extern "C" void kernel_launch(void* const* d_in, const int* in_sizes, int n_in,
                              void* d_out, int out_size)
{
    const float* x    = (const float*)d_in[0];
    const float* cosT = (const float*)d_in[1];
    const float* sinT = (const float*)d_in[2];
    const float* wq   = (const float*)d_in[3];
    const float* wkv  = (const float*)d_in[4];
    const float* wup  = (const float*)d_in[5];
    const float* wout = (const float*)d_in[6];
    float* out = (float*)d_out;

    static bool init = false;
    static bf16 *xh,*xl,*wqTh,*wqTl,*wkvTh,*wkvTl,*wupTh,*wupTl,*woutTh,*woutTl;
    static float *qall,*kvlat,*up,*scores;
    static bf16 *ckvh,*ckvl,*qhh,*qll,*khh,*kll,*vhh,*vll,*vTh,*vTl,*ath,*atl,*aoh,*aol;
    if (!init) {
        cudaGetSymbolAddress((void**)&xh, g_xh);     cudaGetSymbolAddress((void**)&xl, g_xl);
        cudaGetSymbolAddress((void**)&wqTh, g_wqTh); cudaGetSymbolAddress((void**)&wqTl, g_wqTl);
        cudaGetSymbolAddress((void**)&wkvTh, g_wkvTh); cudaGetSymbolAddress((void**)&wkvTl, g_wkvTl);
        cudaGetSymbolAddress((void**)&wupTh, g_wupTh); cudaGetSymbolAddress((void**)&wupTl, g_wupTl);
        cudaGetSymbolAddress((void**)&woutTh, g_woutTh); cudaGetSymbolAddress((void**)&woutTl, g_woutTl);
        cudaGetSymbolAddress((void**)&qall, g_qall); cudaGetSymbolAddress((void**)&kvlat, g_kvlat);
        cudaGetSymbolAddress((void**)&up, g_up);     cudaGetSymbolAddress((void**)&scores, g_scores);
        cudaGetSymbolAddress((void**)&ckvh, g_ckvh); cudaGetSymbolAddress((void**)&ckvl, g_ckvl);
        cudaGetSymbolAddress((void**)&qhh, g_qhh);   cudaGetSymbolAddress((void**)&qll, g_qll);
        cudaGetSymbolAddress((void**)&khh, g_khh);   cudaGetSymbolAddress((void**)&kll, g_kll);
        cudaGetSymbolAddress((void**)&vhh, g_vhh);   cudaGetSymbolAddress((void**)&vll, g_vll);
        cudaGetSymbolAddress((void**)&vTh, g_vTh);   cudaGetSymbolAddress((void**)&vTl, g_vTl);
        cudaGetSymbolAddress((void**)&ath, g_ath);   cudaGetSymbolAddress((void**)&atl, g_atl);
        cudaGetSymbolAddress((void**)&aoh, g_aoh);   cudaGetSymbolAddress((void**)&aol, g_aol);
        cudaFuncSetAttribute((const void*)gemm_mma<128,0,0>,
                             cudaFuncAttributeMaxDynamicSharedMemorySize, 3*(2*128*80 + 2*128*80));
        cudaFuncSetAttribute((const void*)gemm_mma<128,0,1>,
                             cudaFuncAttributeMaxDynamicSharedMemorySize, 3*(2*128*80 + 2*128*80));
        cudaFuncSetAttribute((const void*)gemm_mma<64,0,0>,
                             cudaFuncAttributeMaxDynamicSharedMemorySize, 3*(2*128*80 + 2*64*80));
        cudaFuncSetAttribute((const void*)gemm_mma<64,1,2>,
                             cudaFuncAttributeMaxDynamicSharedMemorySize, 3*(2*128*80 + 2*64*80));
        init = true;
    }
    const int SM128 = 3*(2*128*80 + 2*128*80);   // 122880
    const int SM64  = 3*(2*128*80 + 2*64*80);    // 92160
    const long long LLL = (long long)LL;

    // convert inputs to bf16 hi/lo (weights transposed to [N][K])
    split_k<<<(ML*EE)/256, 256>>>(x, xh, xl, EE, EE);
    wtrans_k<<<dim3(QCOLS/32, EE/32), dim3(32,8)>>>(wq, wqTh, wqTl, EE, QCOLS);
    wtrans_k<<<dim3(KVCOLS/32, EE/32), dim3(32,8)>>>(wkv, wkvTh, wkvTl, EE, KVCOLS);
    wtrans_k<<<dim3(UPCOLS/32, RK/32), dim3(32,8)>>>(wup, wupTh, wupTl, RK, UPCOLS);
    wtrans_k<<<dim3(EE/32, QCOLS/32), dim3(32,8)>>>(wout, woutTh, woutTl, QCOLS, EE);

    // 1) qall = x @ wq (4096x3072x2048)
    gemm_mma<128,0,0><<<dim3(QCOLS/128, ML/128, 1), 256, SM128>>>(
        xh, xl, wqTh, wqTl, qall, nullptr, nullptr,
        EE, EE, EE, QCOLS, 1, 0,0,0,0,0,0);

    // 2) kvlat = x @ wkv (4096x576x2048)
    gemm_mma<64,0,0><<<dim3(KVCOLS/64, ML/128, 1), 256, SM64>>>(
        xh, xl, wkvTh, wkvTl, kvlat, nullptr, nullptr,
        EE, EE, EE, KVCOLS, 1, 0,0,0,0,0,0);

    // split c_kv
    split_k<<<(ML*RK)/256, 256>>>(kvlat, ckvh, ckvl, RK, KVCOLS);

    // 3) up = ckv @ wup (4096x5120x512)
    gemm_mma<128,0,0><<<dim3(UPCOLS/128, ML/128, 1), 256, SM128>>>(
        ckvh, ckvl, wupTh, wupTl, up, nullptr, nullptr,
        RK, RK, RK, UPCOLS, 1, 0,0,0,0,0,0);

    // 4) rope + build q,k,v
    prep_k<<<BB*LL, 256>>>(qall, kvlat, up, cosT, sinT, qhh, qll, khh, kll, vhh, vll);

    // 5) v -> vT
    vtrans_k<<<dim3(LL/32, DTOT/32, BB*HH_), dim3(32,8)>>>(vhh, vll, vTh, vTl);

    // 6) scores = q @ k^T (batched 32, causal block skip)
    gemm_mma<128,0,1><<<dim3(LL/128, LL/128, BB*HH_), 256, SM128>>>(
        qhh, qll, khh, kll, scores, nullptr, nullptr,
        DTOT, DTOT, DTOT, LL, BB*HH_,
        0, LLL*DTOT, 0, LLL*DTOT, 0, LLL*LL);

    // 7) softmax -> attn hi/lo
    softmax_k<<<BB*HH_*LL, 256>>>(scores, ath, atl, 1.0f/sqrtf((float)DTOT));

    // 8) attnout = attn @ vT (batched, K limited by causality), bf16 hi/lo out
    gemm_mma<64,1,2><<<dim3(DTOT/64, LL/128, BB*HH_), 256, SM64>>>(
        ath, atl, vTh, vTl, nullptr, aoh, aol,
        LL, LL, LL, QCOLS, HH_,
        (long long)HH_*LL*LL, LLL*LL,
        (long long)HH_*DTOT*LL, (long long)DTOT*LL,
        LLL*QCOLS, (long long)DTOT);

    // 9) out = attnout @ wout (4096x2048x3072)
    gemm_mma<128,0,0><<<dim3(EE/128, ML/128, 1), 256, SM128>>>(
        aoh, aol, woutTh, woutTl, out, nullptr, nullptr,
        QCOLS, QCOLS, QCOLS, EE, 1, 0,0,0,0,0,0);
}

// round 5
// speedup vs baseline: 2.7173x; 1.0048x over previous
#include <cuda_runtime.h>
#include <cuda_bf16.h>
#include <cstdint>
#include <math.h>

typedef __nv_bfloat16 bf16;

#define BB 2
#define LL 2048
#define EE 2048
#define HH_ 16
#define DH 128
#define RK 512
#define RD 64
#define DTOT 192
#define QCOLS 3072
#define KVCOLS 576
#define UPCOLS 5120
#define ML (BB*LL)

// ===================== scratch (device globals) =====================
__device__ bf16 g_xh[(size_t)ML*EE], g_xl[(size_t)ML*EE];
__device__ bf16 g_wqTh[(size_t)QCOLS*EE], g_wqTl[(size_t)QCOLS*EE];
__device__ bf16 g_wkvTh[(size_t)KVCOLS*EE], g_wkvTl[(size_t)KVCOLS*EE];
__device__ bf16 g_wupTh[(size_t)UPCOLS*RK], g_wupTl[(size_t)UPCOLS*RK];
__device__ bf16 g_woutTh[(size_t)EE*QCOLS], g_woutTl[(size_t)EE*QCOLS];
__device__ float g_qall[(size_t)ML*QCOLS];
__device__ float g_kvlat[(size_t)ML*KVCOLS];
__device__ bf16 g_ckvh[(size_t)ML*RK], g_ckvl[(size_t)ML*RK];
__device__ float g_up[(size_t)ML*UPCOLS];
__device__ bf16 g_qhh[(size_t)BB*HH_*LL*DTOT], g_qll[(size_t)BB*HH_*LL*DTOT];
__device__ bf16 g_khh[(size_t)BB*HH_*LL*DTOT], g_kll[(size_t)BB*HH_*LL*DTOT];
__device__ bf16 g_vhh[(size_t)BB*HH_*LL*DTOT], g_vll[(size_t)BB*HH_*LL*DTOT];
__device__ bf16 g_vTh[(size_t)BB*HH_*DTOT*LL], g_vTl[(size_t)BB*HH_*DTOT*LL];
__device__ float g_scores[(size_t)BB*HH_*LL*LL];           // 537 MB
__device__ bf16 g_ath[(size_t)BB*HH_*LL*LL], g_atl[(size_t)BB*HH_*LL*LL];
__device__ bf16 g_aoh[(size_t)ML*QCOLS], g_aol[(size_t)ML*QCOLS];

// ===================== PTX helpers (baseline sm_80+ features only) =====================
__device__ __forceinline__ uint32_t smem_to_u32(const void* p) {
    uint32_t addr;
    asm("{ .reg .u64 t; cvta.to.shared.u64 t, %1; cvt.u32.u64 %0, t; }"
        : "=r"(addr) : "l"(p));
    return addr;
}
#define CP16(sdst, gsrc) \
    asm volatile("cp.async.cg.shared.global [%0], [%1], 16;" :: "r"(sdst), "l"(gsrc))
#define CP_COMMIT() asm volatile("cp.async.commit_group;" ::: "memory")
#define CP_WAIT1()  asm volatile("cp.async.wait_group 1;" ::: "memory")

__device__ __forceinline__ void ldsm_x4(uint32_t* r, uint32_t a) {
    asm volatile("ldmatrix.sync.aligned.m8n8.x4.shared.b16 {%0,%1,%2,%3}, [%4];"
        : "=r"(r[0]), "=r"(r[1]), "=r"(r[2]), "=r"(r[3]) : "r"(a));
}
__device__ __forceinline__ void mma_bf16(float* c, const uint32_t* a, const uint32_t* b) {
    asm volatile(
        "mma.sync.aligned.m16n8k16.row.col.f32.bf16.bf16.f32 "
        "{%0,%1,%2,%3}, {%4,%5,%6,%7}, {%8,%9}, {%0,%1,%2,%3};"
        : "+f"(c[0]), "+f"(c[1]), "+f"(c[2]), "+f"(c[3])
        : "r"(a[0]), "r"(a[1]), "r"(a[2]), "r"(a[3]), "r"(b[0]), "r"(b[1]));
}
__device__ __forceinline__ void split2(float x, bf16& h, bf16& l) {
    h = __float2bfloat16(x);
    l = __float2bfloat16(x - __bfloat162float(h));
}

// ===================== warp-mma hi/lo GEMM (3-stage pipeline) =====================
// C[M,N] = A[M,K] @ B[N,K]^T, bf16 hi/lo inputs, fp32 accumulate.
// BM=128, BN_ in {128,64}, BK=32, 256 threads (8 warps, 2m x 4n).
// Term-major MMA issue: consecutive MMAs hit different accumulators,
// breaking the HMMA RAW chain on C.
// CAUSAL: 0 none; 1 scores (skip blocks above diagonal); 2 attn@v (K limited).
template<int BN_, int OUTMODE, int CAUSAL>
__global__ void __launch_bounds__(256)
gemm_mma(const bf16* __restrict__ Ah, const bf16* __restrict__ Al,
         const bf16* __restrict__ Bh, const bf16* __restrict__ Bl,
         float* __restrict__ C, bf16* __restrict__ Ch, bf16* __restrict__ Cl,
         int K, int lda, int ldb, int ldc, int hdiv,
         long long sAb, long long sAh2, long long sBb, long long sBh2,
         long long sCb, long long sCh2)
{
    extern __shared__ char smem[];
    const int tid = threadIdx.x;
    const int wid = tid >> 5, lane = tid & 31;

    const int z = blockIdx.z;
    const int zb = z / hdiv, zh = z % hdiv;
    {
        long long ao = (long long)zb*sAb + (long long)zh*sAh2;
        long long bo = (long long)zb*sBb + (long long)zh*sBh2;
        Ah += ao; Al += ao; Bh += bo; Bl += bo;
        long long co = (long long)zb*sCb + (long long)zh*sCh2;
        if (OUTMODE == 0) C += co; else { Ch += co; Cl += co; }
    }

    const int rowBase = blockIdx.y * 128;
    const int colBase = blockIdx.x * BN_;
    if (CAUSAL == 1 && colBase > rowBase + 127) return;

    int Keff = K;
    if (CAUSAL == 2) Keff = min(K, rowBase + 128);
    const int NC = Keff >> 5;

    constexpr int ASZ = 128 * 80;      // one A component tile (128 x 32 bf16, 80B rows)
    constexpr int BSZ = BN_ * 80;
    constexpr int STAGE = 2 * ASZ + 2 * BSZ;
    constexpr int NT = BN_ / 32;       // n-tiles of 8 per warp

    const uint32_t sbu = smem_to_u32(smem);

    const bf16* aH = Ah + (size_t)rowBase * lda;
    const bf16* aL = Al + (size_t)rowBase * lda;
    const bf16* bH = Bh + (size_t)colBase * ldb;
    const bf16* bL = Bl + (size_t)colBase * ldb;

    auto issue = [&](int c) {
        const uint32_t st = sbu + (uint32_t)(c % 3) * STAGE;
        const int k0 = c << 5;
#pragma unroll
        for (int it = 0; it < 2; it++) {           // A: 128 rows x 2 comps
            int idx = tid + it * 256;
            int row = idx >> 2, seg = (idx & 3) << 3;
            size_t go = (size_t)row * lda + k0 + seg;
            uint32_t so = st + row * 80 + (seg << 1);
            CP16(so, aH + go);
            CP16(so + ASZ, aL + go);
        }
#pragma unroll
        for (int it = 0; it < BN_ / 64; it++) {    // B: BN_ rows x 2 comps
            int idx = tid + it * 256;
            int row = idx >> 2, seg = (idx & 3) << 3;
            size_t go = (size_t)row * ldb + k0 + seg;
            uint32_t so = st + 2 * ASZ + row * 80 + (seg << 1);
            CP16(so, bH + go);
            CP16(so + BSZ, bL + go);
        }
        CP_COMMIT();
    };

    float acc[4][NT][4];
#pragma unroll
    for (int mt = 0; mt < 4; mt++)
#pragma unroll
        for (int nt = 0; nt < NT; nt++)
#pragma unroll
            for (int j = 0; j < 4; j++) acc[mt][nt][j] = 0.f;

    const int wm = wid & 1, wn = wid >> 1;

    // prologue: exactly 2 groups committed (real or empty)
    if (0 < NC) issue(0); else CP_COMMIT();
    if (1 < NC) issue(1); else CP_COMMIT();

    for (int c = 0; c < NC; c++) {
        CP_WAIT1();
        __syncthreads();
        if (c + 2 < NC) issue(c + 2); else CP_COMMIT();

        const uint32_t st = sbu + (uint32_t)(c % 3) * STAGE;
        const uint32_t sA = st, sB = st + 2 * ASZ;

        // hoist all B fragments for this chunk (x4 = two n-tiles per ldsm)
        uint32_t bh_[2][NT][2], bl_[2][NT][2];
#pragma unroll
        for (int ks = 0; ks < 2; ks++)
#pragma unroll
            for (int p = 0; p < NT / 2; p++) {
                int rrow = wn * (BN_ / 4) + p * 16 + ((lane >> 4) & 1) * 8 + (lane & 7);
                int ccol = ks * 16 + ((lane >> 3) & 1) * 8;
                uint32_t addr = sB + rrow * 80 + ccol * 2;
                uint32_t t4[4];
                ldsm_x4(t4, addr);
                bh_[ks][2*p][0] = t4[0]; bh_[ks][2*p][1] = t4[1];
                bh_[ks][2*p+1][0] = t4[2]; bh_[ks][2*p+1][1] = t4[3];
                ldsm_x4(t4, addr + BSZ);
                bl_[ks][2*p][0] = t4[0]; bl_[ks][2*p][1] = t4[1];
                bl_[ks][2*p+1][0] = t4[2]; bl_[ks][2*p+1][1] = t4[3];
            }

        // A fragments double-buffered over t = mt*2 + ks
        uint32_t ah2[2][4], al2[2][4];
        {
            int arow = wm * 64 + (lane & 15);
            int acol = (lane >> 4) * 8;
            uint32_t a = sA + arow * 80 + acol * 2;
            ldsm_x4(ah2[0], a); ldsm_x4(al2[0], a + ASZ);
        }
#pragma unroll
        for (int t = 0; t < 8; t++) {
            const int cur = t & 1;
            if (t < 7) {
                int t1 = t + 1, mt1 = t1 >> 1, ks1 = t1 & 1;
                int arow = wm * 64 + mt1 * 16 + (lane & 15);
                int acol = ks1 * 16 + (lane >> 4) * 8;
                uint32_t a = sA + arow * 80 + acol * 2;
                ldsm_x4(ah2[cur ^ 1], a); ldsm_x4(al2[cur ^ 1], a + ASZ);
            }
            const int mt = t >> 1, ks = t & 1;
            // term-major: same-acc MMAs are NT issues apart (no RAW back-to-back)
#pragma unroll
            for (int nt = 0; nt < NT; nt++)
                mma_bf16(acc[mt][nt], ah2[cur], bh_[ks][nt]);
#pragma unroll
            for (int nt = 0; nt < NT; nt++)
                mma_bf16(acc[mt][nt], ah2[cur], bl_[ks][nt]);
#pragma unroll
            for (int nt = 0; nt < NT; nt++)
                mma_bf16(acc[mt][nt], al2[cur], bh_[ks][nt]);
        }
    }

    // epilogue
#pragma unroll
    for (int mt = 0; mt < 4; mt++) {
        size_t r0 = (size_t)rowBase + wm * 64 + mt * 16 + (lane >> 2);
#pragma unroll
        for (int nt = 0; nt < NT; nt++) {
            int c0 = colBase + wn * (BN_ / 4) + nt * 8 + 2 * (lane & 3);
            if (OUTMODE == 0) {
                *(float2*)(C + r0 * ldc + c0) =
                    make_float2(acc[mt][nt][0], acc[mt][nt][1]);
                *(float2*)(C + (r0 + 8) * ldc + c0) =
                    make_float2(acc[mt][nt][2], acc[mt][nt][3]);
            } else {
                bf16 h0, l0, h1, l1;
                split2(acc[mt][nt][0], h0, l0); split2(acc[mt][nt][1], h1, l1);
                *(__nv_bfloat162*)(Ch + r0 * ldc + c0) = __halves2bfloat162(h0, h1);
                *(__nv_bfloat162*)(Cl + r0 * ldc + c0) = __halves2bfloat162(l0, l1);
                split2(acc[mt][nt][2], h0, l0); split2(acc[mt][nt][3], h1, l1);
                *(__nv_bfloat162*)(Ch + (r0 + 8) * ldc + c0) = __halves2bfloat162(h0, h1);
                *(__nv_bfloat162*)(Cl + (r0 + 8) * ldc + c0) = __halves2bfloat162(l0, l1);
            }
        }
    }
}

// ===================== small kernels =====================
__global__ void split_k(const float* __restrict__ in, bf16* __restrict__ oh,
                        bf16* __restrict__ ol, int cols, int ldin)
{
    size_t idx = (size_t)blockIdx.x*256 + threadIdx.x;
    size_t row = idx / cols, col = idx % cols;
    float v = in[row*(size_t)ldin + col];
    bf16 h, l; split2(v, h, l);
    oh[idx] = h; ol[idx] = l;
}

__global__ void wtrans_k(const float* __restrict__ W, bf16* __restrict__ oh,
                         bf16* __restrict__ ol, int Kd, int Nd)
{
    __shared__ float t[32][33];
    int k0 = blockIdx.y*32, n0 = blockIdx.x*32;
    int tx = threadIdx.x, ty = threadIdx.y;
    for (int r = ty; r < 32; r += 8)
        t[r][tx] = W[(size_t)(k0+r)*Nd + n0 + tx];
    __syncthreads();
    for (int r = ty; r < 32; r += 8) {
        float v = t[tx][r];
        bf16 h, l; split2(v, h, l);
        size_t o = (size_t)(n0+r)*Kd + k0 + tx;
        oh[o] = h; ol[o] = l;
    }
}

__global__ void prep_k(const float* __restrict__ qall, const float* __restrict__ kvlat,
                       const float* __restrict__ up, const float* __restrict__ cosT,
                       const float* __restrict__ sinT,
                       bf16* __restrict__ qh, bf16* __restrict__ ql,
                       bf16* __restrict__ kh, bf16* __restrict__ kl,
                       bf16* __restrict__ vh, bf16* __restrict__ vl)
{
    int b = blockIdx.x / LL;
    int l = blockIdx.x % LL;
    int tid = threadIdx.x;
    __shared__ float kr[RD];

    const size_t tokQ  = (size_t)(b*LL + l) * QCOLS;
    const size_t tokKV = (size_t)(b*LL + l) * KVCOLS;
    const size_t tokUP = (size_t)(b*LL + l) * UPCOLS;

    if (tid < RD/2) {
        float x1 = kvlat[tokKV + RK + 2*tid];
        float x2 = kvlat[tokKV + RK + 2*tid + 1];
        float c = cosT[l*(RD/2) + tid];
        float s = sinT[l*(RD/2) + tid];
        kr[2*tid]   = x1*c - x2*s;
        kr[2*tid+1] = x1*s + x2*c;
    }
    __syncthreads();

    for (int idx = tid; idx < HH_*DTOT; idx += blockDim.x) {
        int h = idx / DTOT, d = idx % DTOT;
        size_t o = ((size_t)(b*HH_ + h)*LL + l)*DTOT + d;
        float qv;
        if (d < DH) qv = qall[tokQ + h*DTOT + d];
        else {
            int i = (d - DH) >> 1, odd = (d - DH) & 1;
            float x1 = qall[tokQ + h*DTOT + DH + 2*i];
            float x2 = qall[tokQ + h*DTOT + DH + 2*i + 1];
            float c = cosT[l*(RD/2) + i], s = sinT[l*(RD/2) + i];
            qv = odd ? (x1*s + x2*c) : (x1*c - x2*s);
        }
        bf16 hh, lo; split2(qv, hh, lo); qh[o] = hh; ql[o] = lo;
        float kv = (d < DH) ? up[tokUP + h*320 + d] : kr[d - DH];
        split2(kv, hh, lo); kh[o] = hh; kl[o] = lo;
        float vv = (d < DH) ? up[tokUP + h*320 + DH + d]
                            : up[tokUP + h*320 + 2*DH + (d - DH)];
        split2(vv, hh, lo); vh[o] = hh; vl[o] = lo;
    }
}

__global__ void vtrans_k(const bf16* __restrict__ inh, const bf16* __restrict__ inl,
                         bf16* __restrict__ outh, bf16* __restrict__ outl)
{
    __shared__ bf16 t[32][33];
    int z = blockIdx.z;
    int l0 = blockIdx.x*32, d0 = blockIdx.y*32;
    int tx = threadIdx.x, ty = threadIdx.y;
    const size_t ibase = (size_t)z*LL*DTOT;
    const size_t obase = (size_t)z*DTOT*LL;
#pragma unroll
    for (int a = 0; a < 2; a++) {
        const bf16* in = a ? inl : inh;
        bf16* out = a ? outl : outh;
        for (int r = ty; r < 32; r += 8)
            t[r][tx] = in[ibase + (size_t)(l0+r)*DTOT + d0 + tx];
        __syncthreads();
        for (int r = ty; r < 32; r += 8)
            out[obase + (size_t)(d0+r)*LL + l0 + tx] = t[tx][r];
        __syncthreads();
    }
}

// causal softmax; zero-fill only up to the 128-block boundary (attn@v K-limit)
__global__ void softmax_k(const float* __restrict__ scores, bf16* __restrict__ ah,
                          bf16* __restrict__ al, float scale)
{
    size_t row = blockIdx.x;
    int l = (int)(row % LL);
    const float* p = scores + row*(size_t)LL;
    bf16* oh = ah + row*(size_t)LL;
    bf16* ol = al + row*(size_t)LL;
    int valid = l + 1;
    int zlim = ((l >> 7) + 1) << 7;
    int tid = threadIdx.x;
    __shared__ float red[256];

    float m = -1e30f;
    for (int j = tid; j < valid; j += 256) m = fmaxf(m, p[j]*scale);
    red[tid] = m; __syncthreads();
    for (int s = 128; s > 0; s >>= 1) {
        if (tid < s) red[tid] = fmaxf(red[tid], red[tid+s]);
        __syncthreads();
    }
    m = red[0]; __syncthreads();

    float sum = 0.f;
    for (int j = tid; j < valid; j += 256) sum += __expf(p[j]*scale - m);
    red[tid] = sum; __syncthreads();
    for (int s = 128; s > 0; s >>= 1) {
        if (tid < s) red[tid] += red[tid+s];
        __syncthreads();
    }
    float inv = 1.0f / red[0];
    __syncthreads();

    for (int j = tid; j < valid; j += 256) {
        float e = __expf(p[j]*scale - m) * inv;
        bf16 h, lo; split2(e, h, lo);
        oh[j] = h; ol[j] = lo;
    }
    bf16 z0 = __float2bfloat16(0.f);
    for (int j = valid + tid; j < zlim; j += 256) { oh[j] = z0; ol[j] = z0; }
}

// ===================== launch =====================
extern "C" void kernel_launch(void* const* d_in, const int* in_sizes, int n_in,
                              void* d_out, int out_size)
{
    const float* x    = (const float*)d_in[0];
    const float* cosT = (const float*)d_in[1];
    const float* sinT = (const float*)d_in[2];
    const float* wq   = (const float*)d_in[3];
    const float* wkv  = (const float*)d_in[4];
    const float* wup  = (const float*)d_in[5];
    const float* wout = (const float*)d_in[6];
    float* out = (float*)d_out;

    static bool init = false;
    static bf16 *xh,*xl,*wqTh,*wqTl,*wkvTh,*wkvTl,*wupTh,*wupTl,*woutTh,*woutTl;
    static float *qall,*kvlat,*up,*scores;
    static bf16 *ckvh,*ckvl,*qhh,*qll,*khh,*kll,*vhh,*vll,*vTh,*vTl,*ath,*atl,*aoh,*aol;
    if (!init) {
        cudaGetSymbolAddress((void**)&xh, g_xh);     cudaGetSymbolAddress((void**)&xl, g_xl);
        cudaGetSymbolAddress((void**)&wqTh, g_wqTh); cudaGetSymbolAddress((void**)&wqTl, g_wqTl);
        cudaGetSymbolAddress((void**)&wkvTh, g_wkvTh); cudaGetSymbolAddress((void**)&wkvTl, g_wkvTl);
        cudaGetSymbolAddress((void**)&wupTh, g_wupTh); cudaGetSymbolAddress((void**)&wupTl, g_wupTl);
        cudaGetSymbolAddress((void**)&woutTh, g_woutTh); cudaGetSymbolAddress((void**)&woutTl, g_woutTl);
        cudaGetSymbolAddress((void**)&qall, g_qall); cudaGetSymbolAddress((void**)&kvlat, g_kvlat);
        cudaGetSymbolAddress((void**)&up, g_up);     cudaGetSymbolAddress((void**)&scores, g_scores);
        cudaGetSymbolAddress((void**)&ckvh, g_ckvh); cudaGetSymbolAddress((void**)&ckvl, g_ckvl);
        cudaGetSymbolAddress((void**)&qhh, g_qhh);   cudaGetSymbolAddress((void**)&qll, g_qll);
        cudaGetSymbolAddress((void**)&khh, g_khh);   cudaGetSymbolAddress((void**)&kll, g_kll);
        cudaGetSymbolAddress((void**)&vhh, g_vhh);   cudaGetSymbolAddress((void**)&vll, g_vll);
        cudaGetSymbolAddress((void**)&vTh, g_vTh);   cudaGetSymbolAddress((void**)&vTl, g_vTl);
        cudaGetSymbolAddress((void**)&ath, g_ath);   cudaGetSymbolAddress((void**)&atl, g_atl);
        cudaGetSymbolAddress((void**)&aoh, g_aoh);   cudaGetSymbolAddress((void**)&aol, g_aol);
        cudaFuncSetAttribute((const void*)gemm_mma<128,0,0>,
                             cudaFuncAttributeMaxDynamicSharedMemorySize, 3*(2*128*80 + 2*128*80));
        cudaFuncSetAttribute((const void*)gemm_mma<128,0,1>,
                             cudaFuncAttributeMaxDynamicSharedMemorySize, 3*(2*128*80 + 2*128*80));
        cudaFuncSetAttribute((const void*)gemm_mma<64,0,0>,
                             cudaFuncAttributeMaxDynamicSharedMemorySize, 3*(2*128*80 + 2*64*80));
        cudaFuncSetAttribute((const void*)gemm_mma<64,1,2>,
                             cudaFuncAttributeMaxDynamicSharedMemorySize, 3*(2*128*80 + 2*64*80));
        init = true;
    }
    const int SM128 = 3*(2*128*80 + 2*128*80);   // 122880
    const int SM64  = 3*(2*128*80 + 2*64*80);    // 92160
    const long long LLL = (long long)LL;

    // convert phase (ordered so the 5th launch = big GEMM for ncu -s 5 -c 1)
    split_k<<<(ML*EE)/256, 256>>>(x, xh, xl, EE, EE);                               // 1
    wtrans_k<<<dim3(QCOLS/32, EE/32), dim3(32,8)>>>(wq, wqTh, wqTl, EE, QCOLS);     // 2
    wtrans_k<<<dim3(KVCOLS/32, EE/32), dim3(32,8)>>>(wkv, wkvTh, wkvTl, EE, KVCOLS);// 3
    wtrans_k<<<dim3(UPCOLS/32, RK/32), dim3(32,8)>>>(wup, wupTh, wupTl, RK, UPCOLS);// 4

    // 1) qall = x @ wq (4096x3072x2048)  — 5th launch (profiled)
    gemm_mma<128,0,0><<<dim3(QCOLS/128, ML/128, 1), 256, SM128>>>(
        xh, xl, wqTh, wqTl, qall, nullptr, nullptr,
        EE, EE, EE, QCOLS, 1, 0,0,0,0,0,0);

    wtrans_k<<<dim3(EE/32, QCOLS/32), dim3(32,8)>>>(wout, woutTh, woutTl, QCOLS, EE);

    // 2) kvlat = x @ wkv (4096x576x2048)
    gemm_mma<64,0,0><<<dim3(KVCOLS/64, ML/128, 1), 256, SM64>>>(
        xh, xl, wkvTh, wkvTl, kvlat, nullptr, nullptr,
        EE, EE, EE, KVCOLS, 1, 0,0,0,0,0,0);

    // split c_kv
    split_k<<<(ML*RK)/256, 256>>>(kvlat, ckvh, ckvl, RK, KVCOLS);

    // 3) up = ckv @ wup (4096x5120x512)
    gemm_mma<128,0,0><<<dim3(UPCOLS/128, ML/128, 1), 256, SM128>>>(
        ckvh, ckvl, wupTh, wupTl, up, nullptr, nullptr,
        RK, RK, RK, UPCOLS, 1, 0,0,0,0,0,0);

    // 4) rope + build q,k,v
    prep_k<<<BB*LL, 256>>>(qall, kvlat, up, cosT, sinT, qhh, qll, khh, kll, vhh, vll);

    // 5) v -> vT
    vtrans_k<<<dim3(LL/32, DTOT/32, BB*HH_), dim3(32,8)>>>(vhh, vll, vTh, vTl);

    // 6) scores = q @ k^T (batched 32, causal block skip)
    gemm_mma<128,0,1><<<dim3(LL/128, LL/128, BB*HH_), 256, SM128>>>(
        qhh, qll, khh, kll, scores, nullptr, nullptr,
        DTOT, DTOT, DTOT, LL, BB*HH_,
        0, LLL*DTOT, 0, LLL*DTOT, 0, LLL*LL);

    // 7) softmax -> attn hi/lo
    softmax_k<<<BB*HH_*LL, 256>>>(scores, ath, atl, 1.0f/sqrtf((float)DTOT));

    // 8) attnout = attn @ vT (batched, K limited by causality), bf16 hi/lo out
    gemm_mma<64,1,2><<<dim3(DTOT/64, LL/128, BB*HH_), 256, SM64>>>(
        ath, atl, vTh, vTl, nullptr, aoh, aol,
        LL, LL, LL, QCOLS, HH_,
        (long long)HH_*LL*LL, LLL*LL,
        (long long)HH_*DTOT*LL, (long long)DTOT*LL,
        LLL*QCOLS, (long long)DTOT);

    // 9) out = attnout @ wout (4096x2048x3072)
    gemm_mma<128,0,0><<<dim3(EE/128, ML/128, 1), 256, SM128>>>(
        aoh, aol, woutTh, woutTl, out, nullptr, nullptr,
        QCOLS, QCOLS, QCOLS, EE, 1, 0,0,0,0,0,0);
}

// round 6
// speedup vs baseline: 3.8532x; 1.4180x over previous
#include <cuda_runtime.h>
#include <cuda_fp16.h>
#include <cstdint>
#include <math.h>

typedef __half h16;

#define BB 2
#define LL 2048
#define EE 2048
#define HH_ 16
#define DH 128
#define RK 512
#define RD 64
#define DTOT 192
#define QCOLS 3072
#define KVCOLS 576
#define UPCOLS 5120
#define ML (BB*LL)

// ===================== scratch (device globals) =====================
__device__ h16 g_xh[(size_t)ML*EE], g_xl[(size_t)ML*EE];
__device__ h16 g_wqT[(size_t)QCOLS*EE];
__device__ h16 g_wkvT[(size_t)KVCOLS*EE];
__device__ h16 g_wupT[(size_t)UPCOLS*RK];
__device__ h16 g_woutT[(size_t)EE*QCOLS];
__device__ float g_qall[(size_t)ML*QCOLS];
__device__ float g_kvlat[(size_t)ML*KVCOLS];
__device__ h16 g_ckvh[(size_t)ML*RK], g_ckvl[(size_t)ML*RK];
__device__ float g_up[(size_t)ML*UPCOLS];
__device__ h16 g_qh[(size_t)BB*HH_*LL*DTOT], g_ql[(size_t)BB*HH_*LL*DTOT];
__device__ h16 g_k[(size_t)BB*HH_*LL*DTOT];
__device__ h16 g_v[(size_t)BB*HH_*LL*DTOT];
__device__ h16 g_vT[(size_t)BB*HH_*DTOT*LL];
__device__ float g_scores[(size_t)BB*HH_*LL*LL];           // 537 MB
__device__ h16 g_ath[(size_t)BB*HH_*LL*LL], g_atl[(size_t)BB*HH_*LL*LL];
__device__ h16 g_aoh[(size_t)ML*QCOLS], g_aol[(size_t)ML*QCOLS];

// ===================== PTX helpers (baseline sm_80+ features only) =====================
__device__ __forceinline__ uint32_t smem_to_u32(const void* p) {
    uint32_t addr;
    asm("{ .reg .u64 t; cvta.to.shared.u64 t, %1; cvt.u32.u64 %0, t; }"
        : "=r"(addr) : "l"(p));
    return addr;
}
#define CP16(sdst, gsrc) \
    asm volatile("cp.async.cg.shared.global [%0], [%1], 16;" :: "r"(sdst), "l"(gsrc))
#define CP_COMMIT() asm volatile("cp.async.commit_group;" ::: "memory")
#define CP_WAIT1()  asm volatile("cp.async.wait_group 1;" ::: "memory")

__device__ __forceinline__ void ldsm_x4(uint32_t* r, uint32_t a) {
    asm volatile("ldmatrix.sync.aligned.m8n8.x4.shared.b16 {%0,%1,%2,%3}, [%4];"
        : "=r"(r[0]), "=r"(r[1]), "=r"(r[2]), "=r"(r[3]) : "r"(a));
}
__device__ __forceinline__ void mma_fp16(float* c, const uint32_t* a, const uint32_t* b) {
    asm volatile(
        "mma.sync.aligned.m16n8k16.row.col.f32.f16.f16.f32 "
        "{%0,%1,%2,%3}, {%4,%5,%6,%7}, {%8,%9}, {%0,%1,%2,%3};"
        : "+f"(c[0]), "+f"(c[1]), "+f"(c[2]), "+f"(c[3])
        : "r"(a[0]), "r"(a[1]), "r"(a[2]), "r"(a[3]), "r"(b[0]), "r"(b[1]));
}
__device__ __forceinline__ void split2h(float x, h16& h, h16& l) {
    h = __float2half_rn(x);
    l = __float2half_rn(x - __half2float(h));
}

// ===================== warp-mma fp16 2-term GEMM =====================
// C[M,N] = (Ah + Al)[M,K] @ B[N,K]^T  — A exact fp16 hi/lo pair, B single fp16.
// Error = A @ (B - fp16(B)) ~ 2^-12 relative. fp32 accumulate.
// BM=128, BN_ in {128,64}, BK=32, 256 threads (8 warps, 2m x 4n), 3-stage cp.async.
// CAUSAL: 0 none; 1 scores (skip blocks above diagonal); 2 attn@v (K limited).
template<int BN_, int OUTMODE, int CAUSAL>
__global__ void __launch_bounds__(256)
gemm_mma(const h16* __restrict__ Ah, const h16* __restrict__ Al,
         const h16* __restrict__ B,
         float* __restrict__ C, h16* __restrict__ Ch, h16* __restrict__ Cl,
         int K, int lda, int ldb, int ldc, int hdiv,
         long long sAb, long long sAh2, long long sBb, long long sBh2,
         long long sCb, long long sCh2)
{
    extern __shared__ char smem[];
    const int tid = threadIdx.x;
    const int wid = tid >> 5, lane = tid & 31;

    const int z = blockIdx.z;
    const int zb = z / hdiv, zh = z % hdiv;
    {
        long long ao = (long long)zb*sAb + (long long)zh*sAh2;
        long long bo = (long long)zb*sBb + (long long)zh*sBh2;
        Ah += ao; Al += ao; B += bo;
        long long co = (long long)zb*sCb + (long long)zh*sCh2;
        if (OUTMODE == 0) C += co; else { Ch += co; Cl += co; }
    }

    const int rowBase = blockIdx.y * 128;
    const int colBase = blockIdx.x * BN_;
    if (CAUSAL == 1 && colBase > rowBase + 127) return;

    int Keff = K;
    if (CAUSAL == 2) Keff = min(K, rowBase + 128);
    const int NC = Keff >> 5;

    constexpr int ASZ = 128 * 80;      // one A component tile (128 x 32 fp16, 80B rows)
    constexpr int BSZ = BN_ * 80;
    constexpr int STAGE = 2 * ASZ + BSZ;
    constexpr int NT = BN_ / 32;       // n-tiles of 8 per warp

    const uint32_t sbu = smem_to_u32(smem);

    const h16* aH = Ah + (size_t)rowBase * lda;
    const h16* aL = Al + (size_t)rowBase * lda;
    const h16* bS = B + (size_t)colBase * ldb;

    auto issue = [&](int c) {
        const uint32_t st = sbu + (uint32_t)(c % 3) * STAGE;
        const int k0 = c << 5;
#pragma unroll
        for (int it = 0; it < 2; it++) {           // A: 512 chunk16 positions x 2 comps
            int idx = tid + it * 256;
            int row = idx >> 2, seg = (idx & 3) << 3;
            size_t go = (size_t)row * lda + k0 + seg;
            uint32_t so = st + row * 80 + (seg << 1);
            CP16(so, aH + go);
            CP16(so + ASZ, aL + go);
        }
#pragma unroll
        for (int it = 0; it < BN_ / 64; it++) {    // B: BN_*4 chunk16 positions
            int idx = tid + it * 256;
            int row = idx >> 2, seg = (idx & 3) << 3;
            size_t go = (size_t)row * ldb + k0 + seg;
            uint32_t so = st + 2 * ASZ + row * 80 + (seg << 1);
            CP16(so, bS + go);
        }
        CP_COMMIT();
    };

    float acc[4][NT][4];
#pragma unroll
    for (int mt = 0; mt < 4; mt++)
#pragma unroll
        for (int nt = 0; nt < NT; nt++)
#pragma unroll
            for (int j = 0; j < 4; j++) acc[mt][nt][j] = 0.f;

    const int wm = wid & 1, wn = wid >> 1;

    // prologue: exactly 2 groups committed (real or empty)
    if (0 < NC) issue(0); else CP_COMMIT();
    if (1 < NC) issue(1); else CP_COMMIT();

    for (int c = 0; c < NC; c++) {
        CP_WAIT1();
        __syncthreads();
        if (c + 2 < NC) issue(c + 2); else CP_COMMIT();

        const uint32_t st = sbu + (uint32_t)(c % 3) * STAGE;
        const uint32_t sA = st, sB = st + 2 * ASZ;

        // hoist all B fragments (x4 = two n-tiles per ldsm)
        uint32_t bh_[2][NT][2];
#pragma unroll
        for (int ks = 0; ks < 2; ks++)
#pragma unroll
            for (int p = 0; p < NT / 2; p++) {
                int rrow = wn * (BN_ / 4) + p * 16 + ((lane >> 4) & 1) * 8 + (lane & 7);
                int ccol = ks * 16 + ((lane >> 3) & 1) * 8;
                uint32_t t4[4];
                ldsm_x4(t4, sB + rrow * 80 + ccol * 2);
                bh_[ks][2*p][0] = t4[0]; bh_[ks][2*p][1] = t4[1];
                bh_[ks][2*p+1][0] = t4[2]; bh_[ks][2*p+1][1] = t4[3];
            }

        // A fragments double-buffered over t = mt*2 + ks
        uint32_t ah2[2][4], al2[2][4];
        {
            int arow = wm * 64 + (lane & 15);
            int acol = (lane >> 4) * 8;
            uint32_t a = sA + arow * 80 + acol * 2;
            ldsm_x4(ah2[0], a); ldsm_x4(al2[0], a + ASZ);
        }
#pragma unroll
        for (int t = 0; t < 8; t++) {
            const int cur = t & 1;
            if (t < 7) {
                int t1 = t + 1, mt1 = t1 >> 1, ks1 = t1 & 1;
                int arow = wm * 64 + mt1 * 16 + (lane & 15);
                int acol = ks1 * 16 + (lane >> 4) * 8;
                uint32_t a = sA + arow * 80 + acol * 2;
                ldsm_x4(ah2[cur ^ 1], a); ldsm_x4(al2[cur ^ 1], a + ASZ);
            }
            const int mt = t >> 1, ks = t & 1;
#pragma unroll
            for (int nt = 0; nt < NT; nt++)
                mma_fp16(acc[mt][nt], ah2[cur], bh_[ks][nt]);
#pragma unroll
            for (int nt = 0; nt < NT; nt++)
                mma_fp16(acc[mt][nt], al2[cur], bh_[ks][nt]);
        }
    }

    // epilogue
#pragma unroll
    for (int mt = 0; mt < 4; mt++) {
        size_t r0 = (size_t)rowBase + wm * 64 + mt * 16 + (lane >> 2);
#pragma unroll
        for (int nt = 0; nt < NT; nt++) {
            int c0 = colBase + wn * (BN_ / 4) + nt * 8 + 2 * (lane & 3);
            if (OUTMODE == 0) {
                *(float2*)(C + r0 * ldc + c0) =
                    make_float2(acc[mt][nt][0], acc[mt][nt][1]);
                *(float2*)(C + (r0 + 8) * ldc + c0) =
                    make_float2(acc[mt][nt][2], acc[mt][nt][3]);
            } else {
                h16 h0, l0, h1, l1;
                split2h(acc[mt][nt][0], h0, l0); split2h(acc[mt][nt][1], h1, l1);
                *(__half2*)(Ch + r0 * ldc + c0) = __halves2half2(h0, h1);
                *(__half2*)(Cl + r0 * ldc + c0) = __halves2half2(l0, l1);
                split2h(acc[mt][nt][2], h0, l0); split2h(acc[mt][nt][3], h1, l1);
                *(__half2*)(Ch + (r0 + 8) * ldc + c0) = __halves2half2(h0, h1);
                *(__half2*)(Cl + (r0 + 8) * ldc + c0) = __halves2half2(l0, l1);
            }
        }
    }
}

// ===================== small kernels =====================
// fp32 -> fp16 hi/lo (strided rows)
__global__ void split_k(const float* __restrict__ in, h16* __restrict__ oh,
                        h16* __restrict__ ol, int cols, int ldin)
{
    size_t idx = (size_t)blockIdx.x*256 + threadIdx.x;
    size_t row = idx / cols, col = idx % cols;
    float v = in[row*(size_t)ldin + col];
    h16 h, l; split2h(v, h, l);
    oh[idx] = h; ol[idx] = l;
}

// W[Kd][Nd] fp32 -> WT[Nd][Kd] single fp16
__global__ void wtrans_k(const float* __restrict__ W, h16* __restrict__ o,
                         int Kd, int Nd)
{
    __shared__ float t[32][33];
    int k0 = blockIdx.y*32, n0 = blockIdx.x*32;
    int tx = threadIdx.x, ty = threadIdx.y;
    for (int r = ty; r < 32; r += 8)
        t[r][tx] = W[(size_t)(k0+r)*Nd + n0 + tx];
    __syncthreads();
    for (int r = ty; r < 32; r += 8)
        o[(size_t)(n0+r)*Kd + k0 + tx] = __float2half_rn(t[tx][r]);
}

// RoPE + head split: q hi/lo fp16, k single, v single  (B,H,L,192)
__global__ void prep_k(const float* __restrict__ qall, const float* __restrict__ kvlat,
                       const float* __restrict__ up, const float* __restrict__ cosT,
                       const float* __restrict__ sinT,
                       h16* __restrict__ qh, h16* __restrict__ ql,
                       h16* __restrict__ kk, h16* __restrict__ vv)
{
    int b = blockIdx.x / LL;
    int l = blockIdx.x % LL;
    int tid = threadIdx.x;
    __shared__ float kr[RD];

    const size_t tokQ  = (size_t)(b*LL + l) * QCOLS;
    const size_t tokKV = (size_t)(b*LL + l) * KVCOLS;
    const size_t tokUP = (size_t)(b*LL + l) * UPCOLS;

    if (tid < RD/2) {
        float x1 = kvlat[tokKV + RK + 2*tid];
        float x2 = kvlat[tokKV + RK + 2*tid + 1];
        float c = cosT[l*(RD/2) + tid];
        float s = sinT[l*(RD/2) + tid];
        kr[2*tid]   = x1*c - x2*s;
        kr[2*tid+1] = x1*s + x2*c;
    }
    __syncthreads();

    for (int idx = tid; idx < HH_*DTOT; idx += blockDim.x) {
        int h = idx / DTOT, d = idx % DTOT;
        size_t o = ((size_t)(b*HH_ + h)*LL + l)*DTOT + d;
        float qv;
        if (d < DH) qv = qall[tokQ + h*DTOT + d];
        else {
            int i = (d - DH) >> 1, odd = (d - DH) & 1;
            float x1 = qall[tokQ + h*DTOT + DH + 2*i];
            float x2 = qall[tokQ + h*DTOT + DH + 2*i + 1];
            float c = cosT[l*(RD/2) + i], s = sinT[l*(RD/2) + i];
            qv = odd ? (x1*s + x2*c) : (x1*c - x2*s);
        }
        h16 hh, lo; split2h(qv, hh, lo); qh[o] = hh; ql[o] = lo;
        float kv = (d < DH) ? up[tokUP + h*320 + d] : kr[d - DH];
        kk[o] = __float2half_rn(kv);
        float vvv = (d < DH) ? up[tokUP + h*320 + DH + d]
                             : up[tokUP + h*320 + 2*DH + (d - DH)];
        vv[o] = __float2half_rn(vvv);
    }
}

// v (z, L, 192) -> vT (z, 192, L), single fp16
__global__ void vtrans_k(const h16* __restrict__ in, h16* __restrict__ out)
{
    __shared__ h16 t[32][33];
    int z = blockIdx.z;
    int l0 = blockIdx.x*32, d0 = blockIdx.y*32;
    int tx = threadIdx.x, ty = threadIdx.y;
    const size_t ibase = (size_t)z*LL*DTOT;
    const size_t obase = (size_t)z*DTOT*LL;
    for (int r = ty; r < 32; r += 8)
        t[r][tx] = in[ibase + (size_t)(l0+r)*DTOT + d0 + tx];
    __syncthreads();
    for (int r = ty; r < 32; r += 8)
        out[obase + (size_t)(d0+r)*LL + l0 + tx] = t[tx][r];
}

// causal softmax; fp16 hi/lo out; zero-fill to next 128 boundary
__global__ void softmax_k(const float* __restrict__ scores, h16* __restrict__ ah,
                          h16* __restrict__ al, float scale)
{
    size_t row = blockIdx.x;
    int l = (int)(row % LL);
    const float* p = scores + row*(size_t)LL;
    h16* oh = ah + row*(size_t)LL;
    h16* ol = al + row*(size_t)LL;
    int valid = l + 1;
    int zlim = ((l >> 7) + 1) << 7;
    int tid = threadIdx.x;
    __shared__ float red[256];

    float m = -1e30f;
    for (int j = tid; j < valid; j += 256) m = fmaxf(m, p[j]*scale);
    red[tid] = m; __syncthreads();
    for (int s = 128; s > 0; s >>= 1) {
        if (tid < s) red[tid] = fmaxf(red[tid], red[tid+s]);
        __syncthreads();
    }
    m = red[0]; __syncthreads();

    float sum = 0.f;
    for (int j = tid; j < valid; j += 256) sum += __expf(p[j]*scale - m);
    red[tid] = sum; __syncthreads();
    for (int s = 128; s > 0; s >>= 1) {
        if (tid < s) red[tid] += red[tid+s];
        __syncthreads();
    }
    float inv = 1.0f / red[0];
    __syncthreads();

    for (int j = tid; j < valid; j += 256) {
        float e = __expf(p[j]*scale - m) * inv;
        h16 h, lo; split2h(e, h, lo);
        oh[j] = h; ol[j] = lo;
    }
    h16 z0 = __float2half_rn(0.f);
    for (int j = valid + tid; j < zlim; j += 256) { oh[j] = z0; ol[j] = z0; }
}

// ===================== launch =====================
extern "C" void kernel_launch(void* const* d_in, const int* in_sizes, int n_in,
                              void* d_out, int out_size)
{
    const float* x    = (const float*)d_in[0];
    const float* cosT = (const float*)d_in[1];
    const float* sinT = (const float*)d_in[2];
    const float* wq   = (const float*)d_in[3];
    const float* wkv  = (const float*)d_in[4];
    const float* wup  = (const float*)d_in[5];
    const float* wout = (const float*)d_in[6];
    float* out = (float*)d_out;

    static bool init = false;
    static h16 *xh,*xl,*wqT,*wkvT,*wupT,*woutT;
    static float *qall,*kvlat,*up,*scores;
    static h16 *ckvh,*ckvl,*qh,*ql,*kk,*vv,*vT,*ath,*atl,*aoh,*aol;
    if (!init) {
        cudaGetSymbolAddress((void**)&xh, g_xh);     cudaGetSymbolAddress((void**)&xl, g_xl);
        cudaGetSymbolAddress((void**)&wqT, g_wqT);   cudaGetSymbolAddress((void**)&wkvT, g_wkvT);
        cudaGetSymbolAddress((void**)&wupT, g_wupT); cudaGetSymbolAddress((void**)&woutT, g_woutT);
        cudaGetSymbolAddress((void**)&qall, g_qall); cudaGetSymbolAddress((void**)&kvlat, g_kvlat);
        cudaGetSymbolAddress((void**)&up, g_up);     cudaGetSymbolAddress((void**)&scores, g_scores);
        cudaGetSymbolAddress((void**)&ckvh, g_ckvh); cudaGetSymbolAddress((void**)&ckvl, g_ckvl);
        cudaGetSymbolAddress((void**)&qh, g_qh);     cudaGetSymbolAddress((void**)&ql, g_ql);
        cudaGetSymbolAddress((void**)&kk, g_k);      cudaGetSymbolAddress((void**)&vv, g_v);
        cudaGetSymbolAddress((void**)&vT, g_vT);
        cudaGetSymbolAddress((void**)&ath, g_ath);   cudaGetSymbolAddress((void**)&atl, g_atl);
        cudaGetSymbolAddress((void**)&aoh, g_aoh);   cudaGetSymbolAddress((void**)&aol, g_aol);
        cudaFuncSetAttribute((const void*)gemm_mma<128,0,0>,
                             cudaFuncAttributeMaxDynamicSharedMemorySize, 3*(2*128*80 + 128*80));
        cudaFuncSetAttribute((const void*)gemm_mma<128,0,1>,
                             cudaFuncAttributeMaxDynamicSharedMemorySize, 3*(2*128*80 + 128*80));
        cudaFuncSetAttribute((const void*)gemm_mma<64,0,0>,
                             cudaFuncAttributeMaxDynamicSharedMemorySize, 3*(2*128*80 + 64*80));
        cudaFuncSetAttribute((const void*)gemm_mma<64,1,2>,
                             cudaFuncAttributeMaxDynamicSharedMemorySize, 3*(2*128*80 + 64*80));
        init = true;
    }
    const int SM128 = 3*(2*128*80 + 128*80);   // 92160
    const int SM64  = 3*(2*128*80 + 64*80);    // 76800
    const long long LLL = (long long)LL;

    // convert phase (ordered so the 5th launch = big GEMM for ncu -s 5 -c 1)
    split_k<<<(ML*EE)/256, 256>>>(x, xh, xl, EE, EE);                            // 1
    wtrans_k<<<dim3(QCOLS/32, EE/32), dim3(32,8)>>>(wq, wqT, EE, QCOLS);         // 2
    wtrans_k<<<dim3(KVCOLS/32, EE/32), dim3(32,8)>>>(wkv, wkvT, EE, KVCOLS);     // 3
    wtrans_k<<<dim3(UPCOLS/32, RK/32), dim3(32,8)>>>(wup, wupT, RK, UPCOLS);     // 4

    // 1) qall = x @ wq (4096x3072x2048) — 5th launch (profiled)
    gemm_mma<128,0,0><<<dim3(QCOLS/128, ML/128, 1), 256, SM128>>>(
        xh, xl, wqT, qall, nullptr, nullptr,
        EE, EE, EE, QCOLS, 1, 0,0,0,0,0,0);

    wtrans_k<<<dim3(EE/32, QCOLS/32), dim3(32,8)>>>(wout, woutT, QCOLS, EE);

    // 2) kvlat = x @ wkv (4096x576x2048)
    gemm_mma<64,0,0><<<dim3(KVCOLS/64, ML/128, 1), 256, SM64>>>(
        xh, xl, wkvT, kvlat, nullptr, nullptr,
        EE, EE, EE, KVCOLS, 1, 0,0,0,0,0,0);

    // split c_kv
    split_k<<<(ML*RK)/256, 256>>>(kvlat, ckvh, ckvl, RK, KVCOLS);

    // 3) up = ckv @ wup (4096x5120x512)
    gemm_mma<128,0,0><<<dim3(UPCOLS/128, ML/128, 1), 256, SM128>>>(
        ckvh, ckvl, wupT, up, nullptr, nullptr,
        RK, RK, RK, UPCOLS, 1, 0,0,0,0,0,0);

    // 4) rope + build q (hi/lo), k, v
    prep_k<<<BB*LL, 256>>>(qall, kvlat, up, cosT, sinT, qh, ql, kk, vv);

    // 5) v -> vT
    vtrans_k<<<dim3(LL/32, DTOT/32, BB*HH_), dim3(32,8)>>>(vv, vT);

    // 6) scores = q @ k^T (batched 32, causal block skip)
    gemm_mma<128,0,1><<<dim3(LL/128, LL/128, BB*HH_), 256, SM128>>>(
        qh, ql, kk, scores, nullptr, nullptr,
        DTOT, DTOT, DTOT, LL, BB*HH_,
        0, LLL*DTOT, 0, LLL*DTOT, 0, LLL*LL);

    // 7) softmax -> attn hi/lo
    softmax_k<<<BB*HH_*LL, 256>>>(scores, ath, atl, 1.0f/sqrtf((float)DTOT));

    // 8) attnout = attn @ vT (batched, K limited by causality), fp16 hi/lo out
    gemm_mma<64,1,2><<<dim3(DTOT/64, LL/128, BB*HH_), 256, SM64>>>(
        ath, atl, vT, nullptr, aoh, aol,
        LL, LL, LL, QCOLS, HH_,
        (long long)HH_*LL*LL, LLL*LL,
        (long long)HH_*DTOT*LL, (long long)DTOT*LL,
        LLL*QCOLS, (long long)DTOT);

    // 9) out = attnout @ wout (4096x2048x3072)
    gemm_mma<128,0,0><<<dim3(EE/128, ML/128, 1), 256, SM128>>>(
        aoh, aol, woutT, out, nullptr, nullptr,
        QCOLS, QCOLS, QCOLS, EE, 1, 0,0,0,0,0,0);
}